// round 3
// baseline (speedup 1.0000x reference)
#include <cuda_runtime.h>
#include <math.h>

#define NN 20000
#define EE 400000

// ---------------- scratch (static device globals; ~146 MB total) ----------------
__device__ float g_t1[(size_t)NN * 256];    // Tx1
__device__ float g_t2[(size_t)NN * 256];    // Tx2
__device__ float g_jk[(size_t)NN * 1024];   // JK concat [N, 4*256]
__device__ float g_z[(size_t)NN * 256];     // cls hidden
__device__ float g_deg[NN];
__device__ float g_dis[NN];
__device__ int   g_cnt[NN];
__device__ int   g_cur[NN];
__device__ int   g_starts[NN + 1];
__device__ int   g_srcA[EE];
__device__ float g_wA[EE];
__device__ int   g_is64;

// selector-based pointer resolution (no host-side symbol queries)
#define SEL_EXT 0
#define SEL_T1  1
#define SEL_T2  2
#define SEL_JK  3
#define SEL_Z   4

__device__ __forceinline__ const float* resolve_c(int sel, const float* ext, int off) {
    const float* p;
    switch (sel) {
        case SEL_T1: p = g_t1; break;
        case SEL_T2: p = g_t2; break;
        case SEL_JK: p = g_jk; break;
        case SEL_Z:  p = g_z;  break;
        default:     p = ext;  break;
    }
    return p + off;
}

__device__ __forceinline__ float* resolve_w(int sel, int off) {
    float* p;
    switch (sel) {
        case SEL_T1: p = g_t1; break;
        case SEL_T2: p = g_t2; break;
        case SEL_JK: p = g_jk; break;
        default:     p = g_z;  break;
    }
    return p + off;
}

// edge_index may arrive as int64 or int32 depending on harness dtype handling.
__device__ __forceinline__ int idx_at(const void* ei, int i) {
    if (g_is64) return (int)((const long long*)ei)[i];
    return ((const int*)ei)[i];
}

// ---------------- detect edge_index dtype (deterministic) ----------------
__global__ void detect_kernel(const void* ei) {
    if (threadIdx.x == 0 && blockIdx.x == 0) {
        const long long* p = (const long long*)ei;
        int ok = 1;
        for (int i = 0; i < 64; i++) {
            long long v = p[i];
            if (v < 0 || v >= NN) ok = 0;
        }
        g_is64 = ok;
    }
}

// ---------------- zero init for per-launch accumulators ----------------
__global__ void zero_kernel() {
    int n = blockIdx.x * blockDim.x + threadIdx.x;
    if (n < NN) { g_deg[n] = 0.f; g_cnt[n] = 0; g_cur[n] = 0; }
}

// ---------------- fused edge encoder (PAE parser both halves + cosine) ----------------
// One warp processes 4 edges per iteration. Weights stream through L1 (hot, ~84 KB).
// Per-warp smem: x stage (128 f) + mid stage (512 f).
__global__ __launch_bounds__(256)
void edge_encoder_kernel(const float* __restrict__ edgenet,
                         const float* __restrict__ W1, const float* __restrict__ b1,
                         const float* __restrict__ gam, const float* __restrict__ bet,
                         const float* __restrict__ W2, const float* __restrict__ b2,
                         float* __restrict__ ew)
{
    __shared__ float xbuf[8][128];
    __shared__ float mbuf[8][512];
    const int w = threadIdx.x >> 5;
    const int lane = threadIdx.x & 31;
    const int warpGlobal = blockIdx.x * 8 + w;
    const int nWarps = gridDim.x * 8;
    const float inv = rsqrtf(1.0f + 1e-5f);

    // per-lane epilogue vectors (columns lane*4 .. lane*4+3)
    const float4 b1v = *(const float4*)(b1 + lane * 4);
    const float4 g4  = *(const float4*)(gam + lane * 4);
    const float4 be4 = *(const float4*)(bet + lane * 4);
    const float4 b2v = *(const float4*)(b2 + lane * 4);
    const float sc[4] = {g4.x * inv, g4.y * inv, g4.z * inv, g4.w * inv};
    const float of[4] = {be4.x, be4.y, be4.z, be4.w};
    const float bb1[4] = {b1v.x, b1v.y, b1v.z, b1v.w};
    const float bb2[4] = {b2v.x, b2v.y, b2v.z, b2v.w};

    for (int e0 = warpGlobal * 4; e0 < EE; e0 += nWarps * 4) {
        float h[2][4][4];
#pragma unroll
        for (int half = 0; half < 2; half++) {
            // stage x: 4 edges x 32 features
#pragma unroll
            for (int j = 0; j < 4; j++)
                xbuf[w][j * 32 + lane] = edgenet[(size_t)(e0 + j) * 64 + half * 32 + lane];
            __syncwarp();

            // mid = relu(x @ W1 + b1) * sc + of
            float acc[4][4];
#pragma unroll
            for (int j = 0; j < 4; j++)
#pragma unroll
                for (int c = 0; c < 4; c++) acc[j][c] = 0.f;
#pragma unroll 4
            for (int k = 0; k < 32; k++) {
                const float4 w4 = *(const float4*)(W1 + k * 128 + lane * 4);
#pragma unroll
                for (int j = 0; j < 4; j++) {
                    const float xv = xbuf[w][j * 32 + k];
                    acc[j][0] += xv * w4.x;
                    acc[j][1] += xv * w4.y;
                    acc[j][2] += xv * w4.z;
                    acc[j][3] += xv * w4.w;
                }
            }
            __syncwarp();
#pragma unroll
            for (int j = 0; j < 4; j++)
#pragma unroll
                for (int c = 0; c < 4; c++)
                    mbuf[w][j * 128 + lane * 4 + c] =
                        fmaxf(acc[j][c] + bb1[c], 0.f) * sc[c] + of[c];
            __syncwarp();

            // h = mid @ W2 + b2
            float a2[4][4];
#pragma unroll
            for (int j = 0; j < 4; j++)
#pragma unroll
                for (int c = 0; c < 4; c++) a2[j][c] = 0.f;
#pragma unroll 4
            for (int k = 0; k < 128; k++) {
                const float4 w4 = *(const float4*)(W2 + k * 128 + lane * 4);
#pragma unroll
                for (int j = 0; j < 4; j++) {
                    const float mv = mbuf[w][j * 128 + k];
                    a2[j][0] += mv * w4.x;
                    a2[j][1] += mv * w4.y;
                    a2[j][2] += mv * w4.z;
                    a2[j][3] += mv * w4.w;
                }
            }
#pragma unroll
            for (int j = 0; j < 4; j++)
#pragma unroll
                for (int c = 0; c < 4; c++)
                    h[half][j][c] = a2[j][c] + bb2[c];
            __syncwarp();
        }

        // cosine per edge
#pragma unroll
        for (int j = 0; j < 4; j++) {
            float s11 = 0.f, s22 = 0.f, s12 = 0.f;
#pragma unroll
            for (int c = 0; c < 4; c++) {
                s11 += h[0][j][c] * h[0][j][c];
                s22 += h[1][j][c] * h[1][j][c];
                s12 += h[0][j][c] * h[1][j][c];
            }
#pragma unroll
            for (int off = 16; off > 0; off >>= 1) {
                s11 += __shfl_xor_sync(0xffffffffu, s11, off);
                s22 += __shfl_xor_sync(0xffffffffu, s22, off);
                s12 += __shfl_xor_sync(0xffffffffu, s12, off);
            }
            if (lane == 0) {
                const float n1 = fmaxf(sqrtf(s11), 1e-8f);
                const float n2 = fmaxf(sqrtf(s22), 1e-8f);
                ew[e0 + j] = (s12 / (n1 * n2) + 1.f) * 0.5f;
            }
        }
    }
}

// ---------------- generic tiled SGEMM: C = epi(sum_s A_s @ B_s) ----------------
// BM=64, BN=64, BK=16, 128 threads, 8x4 register tile per thread.
// EPI: 1 = relu(x+bias)*bn_scale + bn_bias ; 2 = relu(x)
template <int EPI, int NSEG>
__global__ __launch_bounds__(128)
void sgemm_kernel(int a0sel, const float* __restrict__ a0ext, int a0off, int lda0,
                  int a1sel, int a1off, int lda1,
                  int a2sel, int a2off, int lda2,
                  const float* __restrict__ B0,
                  const float* __restrict__ B1,
                  const float* __restrict__ B2,
                  int csel, int coff, int ldc,
                  int M, int N, int K,
                  const float* __restrict__ bias,
                  const float* __restrict__ bng,
                  const float* __restrict__ bnb)
{
    __shared__ float As[16][68];
    __shared__ float Bs[16][68];
    const int tid = threadIdx.x;
    const int bm = blockIdx.x * 64;
    const int bn = blockIdx.y * 64;
    const int tx = tid & 15;
    const int ty = tid >> 4;

    float acc[8][4];
#pragma unroll
    for (int i = 0; i < 8; i++)
#pragma unroll
        for (int j = 0; j < 4; j++) acc[i][j] = 0.f;

    const float* Aarr[3];
    Aarr[0] = resolve_c(a0sel, a0ext, a0off);
    Aarr[1] = (NSEG > 1) ? resolve_c(a1sel, nullptr, a1off) : nullptr;
    Aarr[2] = (NSEG > 2) ? resolve_c(a2sel, nullptr, a2off) : nullptr;
    const float* Barr[3] = {B0, B1, B2};
    int ldarr[3] = {lda0, lda1, lda2};

    const int arow = tid >> 2;
    const int acol = (tid & 3) << 2;
    const int brow = tid >> 4;
    const int bcol = (tid & 15) << 2;

#pragma unroll
    for (int s = 0; s < NSEG; s++) {
        const float* A = Aarr[s];
        const float* B = Barr[s];
        const int lda = ldarr[s];
        for (int kk = 0; kk < K; kk += 16) {
#pragma unroll
            for (int h = 0; h < 2; h++) {
                int r = bm + arow + h * 32;
                r = (r < M) ? r : (M - 1);
                const float4 v = *(const float4*)(A + (size_t)r * lda + (kk + acol));
                As[acol + 0][arow + h * 32] = v.x;
                As[acol + 1][arow + h * 32] = v.y;
                As[acol + 2][arow + h * 32] = v.z;
                As[acol + 3][arow + h * 32] = v.w;
            }
#pragma unroll
            for (int h = 0; h < 2; h++) {
                const int kr = kk + brow + h * 8;
                *(float4*)&Bs[brow + h * 8][bcol] =
                    *(const float4*)(B + (size_t)kr * N + (bn + bcol));
            }
            __syncthreads();
#pragma unroll
            for (int k = 0; k < 16; k++) {
                const float4 b4 = *(float4*)&Bs[k][tx << 2];
                const float4 a4 = *(float4*)&As[k][ty << 3];
                const float4 a5 = *(float4*)&As[k][(ty << 3) + 4];
                const float a[8] = {a4.x, a4.y, a4.z, a4.w, a5.x, a5.y, a5.z, a5.w};
                const float b[4] = {b4.x, b4.y, b4.z, b4.w};
#pragma unroll
                for (int i = 0; i < 8; i++)
#pragma unroll
                    for (int j = 0; j < 4; j++)
                        acc[i][j] += a[i] * b[j];
            }
            __syncthreads();
        }
    }

    float* C = resolve_w(csel, coff);
    const int col = bn + (tx << 2);
    float bia[4] = {0, 0, 0, 0}, sca[4] = {1, 1, 1, 1}, ofa[4] = {0, 0, 0, 0};
    if (EPI == 1) {
        const float4 b4 = *(const float4*)(bias + col);
        bia[0] = b4.x; bia[1] = b4.y; bia[2] = b4.z; bia[3] = b4.w;
        const float inv = rsqrtf(1.0f + 1e-5f);
        const float4 g4 = *(const float4*)(bng + col);
        const float4 e4 = *(const float4*)(bnb + col);
        sca[0] = g4.x * inv; sca[1] = g4.y * inv; sca[2] = g4.z * inv; sca[3] = g4.w * inv;
        ofa[0] = e4.x; ofa[1] = e4.y; ofa[2] = e4.z; ofa[3] = e4.w;
    }
#pragma unroll
    for (int i = 0; i < 8; i++) {
        const int r = bm + (ty << 3) + i;
        if (r < M) {
            float4 o;
            float* op = (float*)&o;
#pragma unroll
            for (int j = 0; j < 4; j++) {
                float x = acc[i][j];
                if (EPI == 1) { x = fmaxf(x + bia[j], 0.f); x = x * sca[j] + ofa[j]; }
                if (EPI == 2) x = fmaxf(x, 0.f);
                op[j] = x;
            }
            *(float4*)(C + (size_t)r * ldc + col) = o;
        }
    }
}

// ---------------- degree (by row) + CSR count (by col) ----------------
__global__ void degcnt_kernel(const void* __restrict__ ei, const float* __restrict__ ew)
{
    const int e = blockIdx.x * blockDim.x + threadIdx.x;
    if (e < EE) {
        const int row = idx_at(ei, e);
        const int col = idx_at(ei, e + EE);
        atomicAdd(&g_deg[row], ew[e]);
        atomicAdd(&g_cnt[col], 1);
    }
}

__global__ void dis_kernel()
{
    const int n = blockIdx.x * blockDim.x + threadIdx.x;
    if (n < NN) {
        const float d = g_deg[n];
        g_dis[n] = (d > 0.f) ? rsqrtf(fmaxf(d, 1e-30f)) : 0.f;
    }
}

// single-block exclusive scan of g_cnt -> g_starts
__global__ void scan_kernel()
{
    __shared__ int sm[1024];
    __shared__ int carry;
    const int tid = threadIdx.x;
    if (tid == 0) carry = 0;
    __syncthreads();
    for (int base = 0; base < NN; base += 1024) {
        const int idx = base + tid;
        const int v = (idx < NN) ? g_cnt[idx] : 0;
        sm[tid] = v;
        __syncthreads();
        for (int off = 1; off < 1024; off <<= 1) {
            const int t = (tid >= off) ? sm[tid - off] : 0;
            __syncthreads();
            sm[tid] += t;
            __syncthreads();
        }
        const int c = carry;
        if (idx < NN) g_starts[idx] = c + sm[tid] - v;
        const int tot = sm[1023];
        __syncthreads();
        if (tid == 0) carry = c + tot;
        __syncthreads();
    }
    if (tid == 0) g_starts[NN] = carry;
}

// fill CSR: per-destination edge lists with precomputed norm weight
__global__ void fill_kernel(const void* __restrict__ ei, const float* __restrict__ ew)
{
    const int e = blockIdx.x * blockDim.x + threadIdx.x;
    if (e < EE) {
        const int row = idx_at(ei, e);
        const int col = idx_at(ei, e + EE);
        const int p = g_starts[col] + atomicAdd(&g_cur[col], 1);
        g_srcA[p] = row;
        g_wA[p] = -g_dis[row] * ew[e] * g_dis[col];
    }
}

// ---------------- sparse propagation: out[n,:] = sum_{e: col=n} w_e * X[src_e,:] ----------------
__global__ __launch_bounds__(64)
void prop_kernel(int xsel, const float* __restrict__ xext, int xoff, int ldx,
                 int x0sel, const float* __restrict__ x0ext, int x0off, int ldx0,
                 int osel, int mode)
{
    const float* X  = resolve_c(xsel, xext, xoff);
    const float* X0 = (mode ? resolve_c(x0sel, x0ext, x0off) : nullptr);
    float* out = resolve_w(osel, 0);
    const int n = blockIdx.x;
    const int t = threadIdx.x;
    const int s0 = g_starts[n];
    const int s1 = g_starts[n + 1];
    float4 a = make_float4(0, 0, 0, 0);
    float4 b = make_float4(0, 0, 0, 0);
    int i = s0;
    for (; i + 1 < s1; i += 2) {
        const float w0 = g_wA[i];
        const float w1 = g_wA[i + 1];
        const int r0 = g_srcA[i];
        const int r1 = g_srcA[i + 1];
        const float4 x0 = *(const float4*)(X + (size_t)r0 * ldx + (t << 2));
        const float4 x1 = *(const float4*)(X + (size_t)r1 * ldx + (t << 2));
        a.x += w0 * x0.x; a.y += w0 * x0.y; a.z += w0 * x0.z; a.w += w0 * x0.w;
        b.x += w1 * x1.x; b.y += w1 * x1.y; b.z += w1 * x1.z; b.w += w1 * x1.w;
    }
    if (i < s1) {
        const float w0 = g_wA[i];
        const int r0 = g_srcA[i];
        const float4 x0 = *(const float4*)(X + (size_t)r0 * ldx + (t << 2));
        a.x += w0 * x0.x; a.y += w0 * x0.y; a.z += w0 * x0.z; a.w += w0 * x0.w;
    }
    float4 r = make_float4(a.x + b.x, a.y + b.y, a.z + b.z, a.w + b.w);
    if (mode) {
        const float4 xv = *(const float4*)(X0 + (size_t)n * ldx0 + (t << 2));
        r.x = 2.f * r.x - xv.x;
        r.y = 2.f * r.y - xv.y;
        r.z = 2.f * r.z - xv.z;
        r.w = 2.f * r.w - xv.w;
    }
    *(float4*)(out + (size_t)n * 256 + (t << 2)) = r;
}

// ---------------- final tiny GEMM: logit = z @ cls_w2 + b2 ----------------
__global__ void logits_kernel(const float* __restrict__ w2, const float* __restrict__ b2,
                              float* __restrict__ out)
{
    const int n = blockIdx.x * 8 + (threadIdx.x >> 5);
    const int lane = threadIdx.x & 31;
    if (n >= NN) return;
    float a0 = 0.f, a1 = 0.f;
    const float* z = g_z + (size_t)n * 256;
    for (int i = lane; i < 256; i += 32) {
        const float zv = z[i];
        a0 += zv * w2[2 * i];
        a1 += zv * w2[2 * i + 1];
    }
#pragma unroll
    for (int off = 16; off > 0; off >>= 1) {
        a0 += __shfl_xor_sync(0xffffffffu, a0, off);
        a1 += __shfl_xor_sync(0xffffffffu, a1, off);
    }
    if (lane == 0) {
        out[2 * n] = a0 + b2[0];
        out[2 * n + 1] = a1 + b2[1];
    }
}

// ---------------- launch ----------------
extern "C" void kernel_launch(void* const* d_in, const int* in_sizes, int n_in,
                              void* d_out, int out_size)
{
    (void)in_sizes; (void)n_in; (void)out_size;
    const float* features = (const float*)d_in[0];
    const void*  ei       = d_in[1];
    const float* edgenet  = (const float*)d_in[2];
    const float* cheb     = (const float*)d_in[3];
    const float* en_w1    = (const float*)d_in[4];
    const float* en_b1    = (const float*)d_in[5];
    const float* en_g1    = (const float*)d_in[6];
    const float* en_be1   = (const float*)d_in[7];
    const float* en_w2    = (const float*)d_in[8];
    const float* en_b2    = (const float*)d_in[9];
    const float* cls_w1   = (const float*)d_in[10];
    const float* cls_b1   = (const float*)d_in[11];
    const float* cls_g    = (const float*)d_in[12];
    const float* cls_b    = (const float*)d_in[13];
    const float* cls_w2   = (const float*)d_in[14];
    const float* cls_b2   = (const float*)d_in[15];
    float* out = (float*)d_out;
    float* ew  = out + NN * 2;   // output layout: [logit (N*2), edge_weight (E)]

    detect_kernel<<<1, 32>>>(ei);
    zero_kernel<<<(NN + 255) / 256, 256>>>();

    // ---- fused edge encoder + cosine -> edge weights ----
    edge_encoder_kernel<<<296, 256>>>(edgenet, en_w1, en_b1, en_g1, en_be1,
                                      en_w2, en_b2, ew);

    // ---- graph normalization + CSR build (by destination) ----
    degcnt_kernel<<<(EE + 255) / 256, 256>>>(ei, ew);
    dis_kernel<<<(NN + 255) / 256, 256>>>();
    scan_kernel<<<1, 1024>>>();
    fill_kernel<<<(EE + 255) / 256, 256>>>(ei, ew);

    // ---- stacked ChebConv + JK concat ----
    for (int l = 0; l < 4; l++) {
        const int xsel = (l == 0) ? SEL_EXT : SEL_JK;
        const int xoff = (l == 0) ? 0 : (l - 1) * 256;
        const int ldx  = (l == 0) ? 256 : 1024;
        prop_kernel<<<NN, 64>>>(xsel, features, xoff, ldx,
                                0, nullptr, 0, 0, SEL_T1, 0);
        prop_kernel<<<NN, 64>>>(SEL_T1, nullptr, 0, 256,
                                xsel, features, xoff, ldx, SEL_T2, 1);
        const float* B0 = cheb + (size_t)(l * 3 + 0) * 256 * 256;
        const float* B1 = cheb + (size_t)(l * 3 + 1) * 256 * 256;
        const float* B2 = cheb + (size_t)(l * 3 + 2) * 256 * 256;
        dim3 gC((NN + 63) / 64, 4);
        sgemm_kernel<2, 3><<<gC, 128>>>(xsel, features, xoff, ldx,
                                        SEL_T1, 0, 256,
                                        SEL_T2, 0, 256,
                                        B0, B1, B2,
                                        SEL_JK, l * 256, 1024,
                                        NN, 256, 256, nullptr, nullptr, nullptr);
    }

    // ---- cls head ----
    dim3 gZ((NN + 63) / 64, 4);
    sgemm_kernel<1, 1><<<gZ, 128>>>(SEL_JK, nullptr, 0, 1024,
                                    0, 0, 0, 0, 0, 0,
                                    cls_w1, nullptr, nullptr,
                                    SEL_Z, 0, 256,
                                    NN, 256, 1024, cls_b1, cls_g, cls_b);
    logits_kernel<<<NN / 8, 256>>>(cls_w2, cls_b2, out);
}

// round 4
// speedup vs baseline: 1.0719x; 1.0719x over previous
#include <cuda_runtime.h>
#include <math.h>

#define NN 20000
#define EE 400000

// ---------------- packed f32x2 helpers (sm_100+: FFMA2 only reachable via PTX) ----------
__device__ __forceinline__ unsigned long long pk2(float v) {
    unsigned long long r;
    asm("mov.b64 %0, {%1, %1};" : "=l"(r) : "f"(v));
    return r;
}
__device__ __forceinline__ unsigned long long pk2p(float lo, float hi) {
    unsigned long long r;
    asm("mov.b64 %0, {%1, %2};" : "=l"(r) : "f"(lo), "f"(hi));
    return r;
}
__device__ __forceinline__ float2 upk2(unsigned long long v) {
    float2 r;
    asm("mov.b64 {%0, %1}, %2;" : "=f"(r.x), "=f"(r.y) : "l"(v));
    return r;
}
__device__ __forceinline__ void ffma2(unsigned long long& d, unsigned long long a,
                                      unsigned long long b) {
    asm("fma.rn.f32x2 %0, %1, %2, %0;" : "+l"(d) : "l"(a), "l"(b));
}

// ---------------- scratch (static device globals; ~146 MB total) ----------------
__device__ float g_t1[(size_t)NN * 256];    // Tx1
__device__ float g_t2[(size_t)NN * 256];    // Tx2
__device__ float g_jk[(size_t)NN * 1024];   // JK concat [N, 4*256]
__device__ float g_z[(size_t)NN * 256];     // cls hidden
__device__ float g_deg[NN];
__device__ float g_dis[NN];
__device__ int   g_cnt[NN];
__device__ int   g_cur[NN];
__device__ int   g_starts[NN + 1];
__device__ int   g_srcA[EE];
__device__ float g_wA[EE];
__device__ int   g_is64;

// selector-based pointer resolution (no host-side symbol queries)
#define SEL_EXT 0
#define SEL_T1  1
#define SEL_T2  2
#define SEL_JK  3
#define SEL_Z   4

__device__ __forceinline__ const float* resolve_c(int sel, const float* ext, int off) {
    const float* p;
    switch (sel) {
        case SEL_T1: p = g_t1; break;
        case SEL_T2: p = g_t2; break;
        case SEL_JK: p = g_jk; break;
        case SEL_Z:  p = g_z;  break;
        default:     p = ext;  break;
    }
    return p + off;
}

__device__ __forceinline__ float* resolve_w(int sel, int off) {
    float* p;
    switch (sel) {
        case SEL_T1: p = g_t1; break;
        case SEL_T2: p = g_t2; break;
        case SEL_JK: p = g_jk; break;
        default:     p = g_z;  break;
    }
    return p + off;
}

// edge_index may arrive as int64 or int32 depending on harness dtype handling.
__device__ __forceinline__ int idx_at(const void* ei, int i) {
    if (g_is64) return (int)((const long long*)ei)[i];
    return ((const int*)ei)[i];
}

// ---------------- detect edge_index dtype (deterministic) ----------------
__global__ void detect_kernel(const void* ei) {
    if (threadIdx.x == 0 && blockIdx.x == 0) {
        const long long* p = (const long long*)ei;
        int ok = 1;
        for (int i = 0; i < 64; i++) {
            long long v = p[i];
            if (v < 0 || v >= NN) ok = 0;
        }
        g_is64 = ok;
    }
}

// ---------------- zero init for per-launch accumulators ----------------
__global__ void zero_kernel() {
    int n = blockIdx.x * blockDim.x + threadIdx.x;
    if (n < NN) { g_deg[n] = 0.f; g_cnt[n] = 0; g_cur[n] = 0; }
}

// ---------------- fused edge encoder (PAE parser both halves + cosine) ----------------
// One warp processes 4 edges per iteration; f32x2 packed FMA on the column dim.
__global__ __launch_bounds__(256)
void edge_encoder_kernel(const float* __restrict__ edgenet,
                         const float* __restrict__ W1, const float* __restrict__ b1,
                         const float* __restrict__ gam, const float* __restrict__ bet,
                         const float* __restrict__ W2, const float* __restrict__ b2,
                         float* __restrict__ ew)
{
    __shared__ float xbuf[8][128];
    __shared__ float mbuf[8][512];
    const int w = threadIdx.x >> 5;
    const int lane = threadIdx.x & 31;
    const int warpGlobal = blockIdx.x * 8 + w;
    const int nWarps = gridDim.x * 8;
    const float inv = rsqrtf(1.0f + 1e-5f);

    // per-lane epilogue vectors (columns lane*4 .. lane*4+3)
    const float4 b1v = *(const float4*)(b1 + lane * 4);
    const float4 g4  = *(const float4*)(gam + lane * 4);
    const float4 be4 = *(const float4*)(bet + lane * 4);
    const float4 b2v = *(const float4*)(b2 + lane * 4);
    const float sc[4] = {g4.x * inv, g4.y * inv, g4.z * inv, g4.w * inv};
    const float of[4] = {be4.x, be4.y, be4.z, be4.w};
    const float bb1[4] = {b1v.x, b1v.y, b1v.z, b1v.w};
    const float bb2[4] = {b2v.x, b2v.y, b2v.z, b2v.w};

    for (int e0 = warpGlobal * 4; e0 < EE; e0 += nWarps * 4) {
        float h[2][4][4];
#pragma unroll
        for (int half = 0; half < 2; half++) {
            // stage x: 4 edges x 32 features
#pragma unroll
            for (int j = 0; j < 4; j++)
                xbuf[w][j * 32 + lane] = edgenet[(size_t)(e0 + j) * 64 + half * 32 + lane];
            __syncwarp();

            // mid = relu(x @ W1 + b1) * sc + of   (f32x2: pairs over columns)
            unsigned long long acc[4][2];
#pragma unroll
            for (int j = 0; j < 4; j++) { acc[j][0] = 0ULL; acc[j][1] = 0ULL; }
#pragma unroll 4
            for (int k = 0; k < 32; k++) {
                const float4 w4 = *(const float4*)(W1 + k * 128 + lane * 4);
                const unsigned long long wp0 = pk2p(w4.x, w4.y);
                const unsigned long long wp1 = pk2p(w4.z, w4.w);
#pragma unroll
                for (int j = 0; j < 4; j++) {
                    const unsigned long long xs = pk2(xbuf[w][j * 32 + k]);
                    ffma2(acc[j][0], xs, wp0);
                    ffma2(acc[j][1], xs, wp1);
                }
            }
            __syncwarp();
#pragma unroll
            for (int j = 0; j < 4; j++) {
                const float2 u0 = upk2(acc[j][0]);
                const float2 u1 = upk2(acc[j][1]);
                const float v[4] = {u0.x, u0.y, u1.x, u1.y};
#pragma unroll
                for (int c = 0; c < 4; c++)
                    mbuf[w][j * 128 + lane * 4 + c] =
                        fmaxf(v[c] + bb1[c], 0.f) * sc[c] + of[c];
            }
            __syncwarp();

            // h = mid @ W2 + b2   (f32x2)
            unsigned long long a2[4][2];
#pragma unroll
            for (int j = 0; j < 4; j++) { a2[j][0] = 0ULL; a2[j][1] = 0ULL; }
#pragma unroll 4
            for (int k = 0; k < 128; k++) {
                const float4 w4 = *(const float4*)(W2 + k * 128 + lane * 4);
                const unsigned long long wp0 = pk2p(w4.x, w4.y);
                const unsigned long long wp1 = pk2p(w4.z, w4.w);
#pragma unroll
                for (int j = 0; j < 4; j++) {
                    const unsigned long long mv = pk2(mbuf[w][j * 128 + k]);
                    ffma2(a2[j][0], mv, wp0);
                    ffma2(a2[j][1], mv, wp1);
                }
            }
#pragma unroll
            for (int j = 0; j < 4; j++) {
                const float2 u0 = upk2(a2[j][0]);
                const float2 u1 = upk2(a2[j][1]);
                h[half][j][0] = u0.x + bb2[0];
                h[half][j][1] = u0.y + bb2[1];
                h[half][j][2] = u1.x + bb2[2];
                h[half][j][3] = u1.y + bb2[3];
            }
            __syncwarp();
        }

        // cosine per edge
#pragma unroll
        for (int j = 0; j < 4; j++) {
            float s11 = 0.f, s22 = 0.f, s12 = 0.f;
#pragma unroll
            for (int c = 0; c < 4; c++) {
                s11 += h[0][j][c] * h[0][j][c];
                s22 += h[1][j][c] * h[1][j][c];
                s12 += h[0][j][c] * h[1][j][c];
            }
#pragma unroll
            for (int off = 16; off > 0; off >>= 1) {
                s11 += __shfl_xor_sync(0xffffffffu, s11, off);
                s22 += __shfl_xor_sync(0xffffffffu, s22, off);
                s12 += __shfl_xor_sync(0xffffffffu, s12, off);
            }
            if (lane == 0) {
                const float n1 = fmaxf(sqrtf(s11), 1e-8f);
                const float n2 = fmaxf(sqrtf(s22), 1e-8f);
                ew[e0 + j] = (s12 / (n1 * n2) + 1.f) * 0.5f;
            }
        }
    }
}

// ---------------- generic tiled SGEMM: C = epi(sum_s A_s @ B_s) ----------------
// BM=64, BN=64, BK=16, 128 threads, 8x4 register tile, f32x2 packed FMA.
// EPI: 1 = relu(x+bias)*bn_scale + bn_bias ; 2 = relu(x)
template <int EPI, int NSEG>
__global__ __launch_bounds__(128)
void sgemm_kernel(int a0sel, const float* __restrict__ a0ext, int a0off, int lda0,
                  int a1sel, int a1off, int lda1,
                  int a2sel, int a2off, int lda2,
                  const float* __restrict__ B0,
                  const float* __restrict__ B1,
                  const float* __restrict__ B2,
                  int csel, int coff, int ldc,
                  int M, int N, int K,
                  const float* __restrict__ bias,
                  const float* __restrict__ bng,
                  const float* __restrict__ bnb)
{
    __shared__ float As[16][68];
    __shared__ float Bs[16][68];
    const int tid = threadIdx.x;
    const int bm = blockIdx.x * 64;
    const int bn = blockIdx.y * 64;
    const int tx = tid & 15;
    const int ty = tid >> 4;

    // acc pairs over row dim: pair p covers rows (2p, 2p+1) of this thread's 8 rows
    unsigned long long acc2[4][4];
#pragma unroll
    for (int p = 0; p < 4; p++)
#pragma unroll
        for (int j = 0; j < 4; j++) acc2[p][j] = 0ULL;

    const float* Aarr[3];
    Aarr[0] = resolve_c(a0sel, a0ext, a0off);
    Aarr[1] = (NSEG > 1) ? resolve_c(a1sel, nullptr, a1off) : nullptr;
    Aarr[2] = (NSEG > 2) ? resolve_c(a2sel, nullptr, a2off) : nullptr;
    const float* Barr[3] = {B0, B1, B2};
    int ldarr[3] = {lda0, lda1, lda2};

    const int arow = tid >> 2;
    const int acol = (tid & 3) << 2;
    const int brow = tid >> 4;
    const int bcol = (tid & 15) << 2;

#pragma unroll
    for (int s = 0; s < NSEG; s++) {
        const float* A = Aarr[s];
        const float* B = Barr[s];
        const int lda = ldarr[s];
        for (int kk = 0; kk < K; kk += 16) {
#pragma unroll
            for (int h = 0; h < 2; h++) {
                int r = bm + arow + h * 32;
                r = (r < M) ? r : (M - 1);
                const float4 v = *(const float4*)(A + (size_t)r * lda + (kk + acol));
                As[acol + 0][arow + h * 32] = v.x;
                As[acol + 1][arow + h * 32] = v.y;
                As[acol + 2][arow + h * 32] = v.z;
                As[acol + 3][arow + h * 32] = v.w;
            }
#pragma unroll
            for (int h = 0; h < 2; h++) {
                const int kr = kk + brow + h * 8;
                *(float4*)&Bs[brow + h * 8][bcol] =
                    *(const float4*)(B + (size_t)kr * N + (bn + bcol));
            }
            __syncthreads();
#pragma unroll
            for (int k = 0; k < 16; k++) {
                const float4 b4 = *(float4*)&Bs[k][tx << 2];
                const float4 a4 = *(float4*)&As[k][ty << 3];
                const float4 a5 = *(float4*)&As[k][(ty << 3) + 4];
                const unsigned long long ap[4] = {
                    pk2p(a4.x, a4.y), pk2p(a4.z, a4.w),
                    pk2p(a5.x, a5.y), pk2p(a5.z, a5.w)};
                const unsigned long long bs[4] = {
                    pk2(b4.x), pk2(b4.y), pk2(b4.z), pk2(b4.w)};
#pragma unroll
                for (int p = 0; p < 4; p++)
#pragma unroll
                    for (int j = 0; j < 4; j++)
                        ffma2(acc2[p][j], ap[p], bs[j]);
            }
            __syncthreads();
        }
    }

    float* C = resolve_w(csel, coff);
    const int col = bn + (tx << 2);
    float bia[4] = {0, 0, 0, 0}, sca[4] = {1, 1, 1, 1}, ofa[4] = {0, 0, 0, 0};
    if (EPI == 1) {
        const float4 b4 = *(const float4*)(bias + col);
        bia[0] = b4.x; bia[1] = b4.y; bia[2] = b4.z; bia[3] = b4.w;
        const float inv = rsqrtf(1.0f + 1e-5f);
        const float4 g4 = *(const float4*)(bng + col);
        const float4 e4 = *(const float4*)(bnb + col);
        sca[0] = g4.x * inv; sca[1] = g4.y * inv; sca[2] = g4.z * inv; sca[3] = g4.w * inv;
        ofa[0] = e4.x; ofa[1] = e4.y; ofa[2] = e4.z; ofa[3] = e4.w;
    }
#pragma unroll
    for (int p = 0; p < 4; p++) {
        float2 u[4];
#pragma unroll
        for (int j = 0; j < 4; j++) u[j] = upk2(acc2[p][j]);
#pragma unroll
        for (int half = 0; half < 2; half++) {
            const int r = bm + (ty << 3) + 2 * p + half;
            if (r < M) {
                float4 o;
                float* op = (float*)&o;
#pragma unroll
                for (int j = 0; j < 4; j++) {
                    float x = half ? u[j].y : u[j].x;
                    if (EPI == 1) { x = fmaxf(x + bia[j], 0.f); x = x * sca[j] + ofa[j]; }
                    if (EPI == 2) x = fmaxf(x, 0.f);
                    op[j] = x;
                }
                *(float4*)(C + (size_t)r * ldc + col) = o;
            }
        }
    }
}

// ---------------- degree (by row) + CSR count (by col) ----------------
__global__ void degcnt_kernel(const void* __restrict__ ei, const float* __restrict__ ew)
{
    const int e = blockIdx.x * blockDim.x + threadIdx.x;
    if (e < EE) {
        const int row = idx_at(ei, e);
        const int col = idx_at(ei, e + EE);
        atomicAdd(&g_deg[row], ew[e]);
        atomicAdd(&g_cnt[col], 1);
    }
}

__global__ void dis_kernel()
{
    const int n = blockIdx.x * blockDim.x + threadIdx.x;
    if (n < NN) {
        const float d = g_deg[n];
        g_dis[n] = (d > 0.f) ? rsqrtf(fmaxf(d, 1e-30f)) : 0.f;
    }
}

// single-block exclusive scan of g_cnt -> g_starts
__global__ void scan_kernel()
{
    __shared__ int sm[1024];
    __shared__ int carry;
    const int tid = threadIdx.x;
    if (tid == 0) carry = 0;
    __syncthreads();
    for (int base = 0; base < NN; base += 1024) {
        const int idx = base + tid;
        const int v = (idx < NN) ? g_cnt[idx] : 0;
        sm[tid] = v;
        __syncthreads();
        for (int off = 1; off < 1024; off <<= 1) {
            const int t = (tid >= off) ? sm[tid - off] : 0;
            __syncthreads();
            sm[tid] += t;
            __syncthreads();
        }
        const int c = carry;
        if (idx < NN) g_starts[idx] = c + sm[tid] - v;
        const int tot = sm[1023];
        __syncthreads();
        if (tid == 0) carry = c + tot;
        __syncthreads();
    }
    if (tid == 0) g_starts[NN] = carry;
}

// fill CSR: per-destination edge lists with precomputed norm weight
__global__ void fill_kernel(const void* __restrict__ ei, const float* __restrict__ ew)
{
    const int e = blockIdx.x * blockDim.x + threadIdx.x;
    if (e < EE) {
        const int row = idx_at(ei, e);
        const int col = idx_at(ei, e + EE);
        const int p = g_starts[col] + atomicAdd(&g_cur[col], 1);
        g_srcA[p] = row;
        g_wA[p] = -g_dis[row] * ew[e] * g_dis[col];
    }
}

// ---------------- sparse propagation: out[n,:] = sum_{e: col=n} w_e * X[src_e,:] ----------------
__global__ __launch_bounds__(64)
void prop_kernel(int xsel, const float* __restrict__ xext, int xoff, int ldx,
                 int x0sel, const float* __restrict__ x0ext, int x0off, int ldx0,
                 int osel, int mode)
{
    const float* X  = resolve_c(xsel, xext, xoff);
    const float* X0 = (mode ? resolve_c(x0sel, x0ext, x0off) : nullptr);
    float* out = resolve_w(osel, 0);
    const int n = blockIdx.x;
    const int t = threadIdx.x;
    const int s0 = g_starts[n];
    const int s1 = g_starts[n + 1];
    float4 a = make_float4(0, 0, 0, 0);
    float4 b = make_float4(0, 0, 0, 0);
    int i = s0;
    for (; i + 1 < s1; i += 2) {
        const float w0 = g_wA[i];
        const float w1 = g_wA[i + 1];
        const int r0 = g_srcA[i];
        const int r1 = g_srcA[i + 1];
        const float4 x0 = *(const float4*)(X + (size_t)r0 * ldx + (t << 2));
        const float4 x1 = *(const float4*)(X + (size_t)r1 * ldx + (t << 2));
        a.x += w0 * x0.x; a.y += w0 * x0.y; a.z += w0 * x0.z; a.w += w0 * x0.w;
        b.x += w1 * x1.x; b.y += w1 * x1.y; b.z += w1 * x1.z; b.w += w1 * x1.w;
    }
    if (i < s1) {
        const float w0 = g_wA[i];
        const int r0 = g_srcA[i];
        const float4 x0 = *(const float4*)(X + (size_t)r0 * ldx + (t << 2));
        a.x += w0 * x0.x; a.y += w0 * x0.y; a.z += w0 * x0.z; a.w += w0 * x0.w;
    }
    float4 r = make_float4(a.x + b.x, a.y + b.y, a.z + b.z, a.w + b.w);
    if (mode) {
        const float4 xv = *(const float4*)(X0 + (size_t)n * ldx0 + (t << 2));
        r.x = 2.f * r.x - xv.x;
        r.y = 2.f * r.y - xv.y;
        r.z = 2.f * r.z - xv.z;
        r.w = 2.f * r.w - xv.w;
    }
    *(float4*)(out + (size_t)n * 256 + (t << 2)) = r;
}

// ---------------- final tiny GEMM: logit = z @ cls_w2 + b2 ----------------
__global__ void logits_kernel(const float* __restrict__ w2, const float* __restrict__ b2,
                              float* __restrict__ out)
{
    const int n = blockIdx.x * 8 + (threadIdx.x >> 5);
    const int lane = threadIdx.x & 31;
    if (n >= NN) return;
    float a0 = 0.f, a1 = 0.f;
    const float* z = g_z + (size_t)n * 256;
    for (int i = lane; i < 256; i += 32) {
        const float zv = z[i];
        a0 += zv * w2[2 * i];
        a1 += zv * w2[2 * i + 1];
    }
#pragma unroll
    for (int off = 16; off > 0; off >>= 1) {
        a0 += __shfl_xor_sync(0xffffffffu, a0, off);
        a1 += __shfl_xor_sync(0xffffffffu, a1, off);
    }
    if (lane == 0) {
        out[2 * n] = a0 + b2[0];
        out[2 * n + 1] = a1 + b2[1];
    }
}

// ---------------- launch ----------------
extern "C" void kernel_launch(void* const* d_in, const int* in_sizes, int n_in,
                              void* d_out, int out_size)
{
    (void)in_sizes; (void)n_in; (void)out_size;
    const float* features = (const float*)d_in[0];
    const void*  ei       = d_in[1];
    const float* edgenet  = (const float*)d_in[2];
    const float* cheb     = (const float*)d_in[3];
    const float* en_w1    = (const float*)d_in[4];
    const float* en_b1    = (const float*)d_in[5];
    const float* en_g1    = (const float*)d_in[6];
    const float* en_be1   = (const float*)d_in[7];
    const float* en_w2    = (const float*)d_in[8];
    const float* en_b2    = (const float*)d_in[9];
    const float* cls_w1   = (const float*)d_in[10];
    const float* cls_b1   = (const float*)d_in[11];
    const float* cls_g    = (const float*)d_in[12];
    const float* cls_b    = (const float*)d_in[13];
    const float* cls_w2   = (const float*)d_in[14];
    const float* cls_b2   = (const float*)d_in[15];
    float* out = (float*)d_out;
    float* ew  = out + NN * 2;   // output layout: [logit (N*2), edge_weight (E)]

    detect_kernel<<<1, 32>>>(ei);
    zero_kernel<<<(NN + 255) / 256, 256>>>();

    // ---- fused edge encoder + cosine -> edge weights ----
    edge_encoder_kernel<<<296, 256>>>(edgenet, en_w1, en_b1, en_g1, en_be1,
                                      en_w2, en_b2, ew);

    // ---- graph normalization + CSR build (by destination) ----
    degcnt_kernel<<<(EE + 255) / 256, 256>>>(ei, ew);
    dis_kernel<<<(NN + 255) / 256, 256>>>();
    scan_kernel<<<1, 1024>>>();
    fill_kernel<<<(EE + 255) / 256, 256>>>(ei, ew);

    // ---- stacked ChebConv + JK concat ----
    for (int l = 0; l < 4; l++) {
        const int xsel = (l == 0) ? SEL_EXT : SEL_JK;
        const int xoff = (l == 0) ? 0 : (l - 1) * 256;
        const int ldx  = (l == 0) ? 256 : 1024;
        prop_kernel<<<NN, 64>>>(xsel, features, xoff, ldx,
                                0, nullptr, 0, 0, SEL_T1, 0);
        prop_kernel<<<NN, 64>>>(SEL_T1, nullptr, 0, 256,
                                xsel, features, xoff, ldx, SEL_T2, 1);
        const float* B0 = cheb + (size_t)(l * 3 + 0) * 256 * 256;
        const float* B1 = cheb + (size_t)(l * 3 + 1) * 256 * 256;
        const float* B2 = cheb + (size_t)(l * 3 + 2) * 256 * 256;
        dim3 gC((NN + 63) / 64, 4);
        sgemm_kernel<2, 3><<<gC, 128>>>(xsel, features, xoff, ldx,
                                        SEL_T1, 0, 256,
                                        SEL_T2, 0, 256,
                                        B0, B1, B2,
                                        SEL_JK, l * 256, 1024,
                                        NN, 256, 256, nullptr, nullptr, nullptr);
    }

    // ---- cls head ----
    dim3 gZ((NN + 63) / 64, 4);
    sgemm_kernel<1, 1><<<gZ, 128>>>(SEL_JK, nullptr, 0, 1024,
                                    0, 0, 0, 0, 0, 0,
                                    cls_w1, nullptr, nullptr,
                                    SEL_Z, 0, 256,
                                    NN, 256, 1024, cls_b1, cls_g, cls_b);
    logits_kernel<<<NN / 8, 256>>>(cls_w2, cls_b2, out);
}

// round 6
// speedup vs baseline: 1.1897x; 1.1099x over previous
#include <cuda_runtime.h>
#include <cuda_bf16.h>
#include <math.h>
#include <stdint.h>

#define NN 20000
#define EE 400000

// ---------------- packed f32x2 helpers ----------------
__device__ __forceinline__ unsigned long long pk2(float v) {
    unsigned long long r;
    asm("mov.b64 %0, {%1, %1};" : "=l"(r) : "f"(v));
    return r;
}
__device__ __forceinline__ unsigned long long pk2p(float lo, float hi) {
    unsigned long long r;
    asm("mov.b64 %0, {%1, %2};" : "=l"(r) : "f"(lo), "f"(hi));
    return r;
}
__device__ __forceinline__ float2 upk2(unsigned long long v) {
    float2 r;
    asm("mov.b64 {%0, %1}, %2;" : "=f"(r.x), "=f"(r.y) : "l"(v));
    return r;
}
__device__ __forceinline__ void ffma2(unsigned long long& d, unsigned long long a,
                                      unsigned long long b) {
    asm("fma.rn.f32x2 %0, %1, %2, %0;" : "+l"(d) : "l"(a), "l"(b));
}

// ---------------- mma.sync / ldmatrix helpers (baseline PTX, ok on compute_103) ------
__device__ __forceinline__ uint32_t smem_u32(const void* p) {
    uint32_t a;
    asm("{ .reg .u64 t; cvta.to.shared.u64 t, %1; cvt.u32.u64 %0, t; }" : "=r"(a) : "l"(p));
    return a;
}
__device__ __forceinline__ void ldm_x4(uint32_t* r, uint32_t addr) {
    asm volatile("ldmatrix.sync.aligned.m8n8.x4.shared.b16 {%0,%1,%2,%3}, [%4];"
                 : "=r"(r[0]), "=r"(r[1]), "=r"(r[2]), "=r"(r[3]) : "r"(addr));
}
__device__ __forceinline__ void ldm_x2t(uint32_t* r, uint32_t addr) {
    asm volatile("ldmatrix.sync.aligned.m8n8.x2.trans.shared.b16 {%0,%1}, [%2];"
                 : "=r"(r[0]), "=r"(r[1]) : "r"(addr));
}
__device__ __forceinline__ void mma16816(float* c, const uint32_t* a, const uint32_t* b) {
    asm volatile(
        "mma.sync.aligned.m16n8k16.row.col.f32.bf16.bf16.f32 "
        "{%0,%1,%2,%3}, {%4,%5,%6,%7}, {%8,%9}, {%0,%1,%2,%3};"
        : "+f"(c[0]), "+f"(c[1]), "+f"(c[2]), "+f"(c[3])
        : "r"(a[0]), "r"(a[1]), "r"(a[2]), "r"(a[3]), "r"(b[0]), "r"(b[1]));
}
__device__ __forceinline__ void split_bf16(float v, __nv_bfloat16& h, __nv_bfloat16& l) {
    h = __float2bfloat16(v);
    l = __float2bfloat16(v - __bfloat162float(h));
}

// ---------------- scratch ----------------
__device__ float g_t1[(size_t)NN * 256];
__device__ float g_t2[(size_t)NN * 256];
__device__ float g_jk[(size_t)NN * 1024];
__device__ float g_z[(size_t)NN * 256];
__device__ float g_deg[NN];
__device__ float g_dis[NN];
__device__ int   g_cnt[NN];
__device__ int   g_cur[NN];
__device__ int   g_starts[NN + 1];
__device__ int   g_srcA[EE];
__device__ float g_wA[EE];
__device__ int   g_is64;

#define SEL_EXT 0
#define SEL_T1  1
#define SEL_T2  2
#define SEL_JK  3
#define SEL_Z   4

__device__ __forceinline__ const float* resolve_c(int sel, const float* ext, int off) {
    const float* p;
    switch (sel) {
        case SEL_T1: p = g_t1; break;
        case SEL_T2: p = g_t2; break;
        case SEL_JK: p = g_jk; break;
        case SEL_Z:  p = g_z;  break;
        default:     p = ext;  break;
    }
    return p + off;
}
__device__ __forceinline__ float* resolve_w(int sel, int off) {
    float* p;
    switch (sel) {
        case SEL_T1: p = g_t1; break;
        case SEL_T2: p = g_t2; break;
        case SEL_JK: p = g_jk; break;
        default:     p = g_z;  break;
    }
    return p + off;
}
__device__ __forceinline__ int idx_at(const void* ei, int i) {
    if (g_is64) return (int)((const long long*)ei)[i];
    return ((const int*)ei)[i];
}

__global__ void detect_kernel(const void* ei) {
    if (threadIdx.x == 0 && blockIdx.x == 0) {
        const long long* p = (const long long*)ei;
        int ok = 1;
        for (int i = 0; i < 64; i++) {
            long long v = p[i];
            if (v < 0 || v >= NN) ok = 0;
        }
        g_is64 = ok;
    }
}

__global__ void zero_kernel() {
    int n = blockIdx.x * blockDim.x + threadIdx.x;
    if (n < NN) { g_deg[n] = 0.f; g_cnt[n] = 0; g_cur[n] = 0; }
}

// ================= split-bf16 HMMA GEMM for node-side matrices ==================
// C[M, 256] = epi( sum_s A_s[M, K] @ W_s[K, 256] )
// Tile 128x128, 256 threads (8 warps, 4x2), K-chunk 32.
// EPI: 1 = relu(x+bias)*bn_scale + bn_bias ; 2 = relu(x)
#define APAD 40   // row stride (bf16 elems) for A smem: 80B, conflict-free ldmatrix
#define BPAD 136  // row stride for B smem: 272B

template <int EPI>
__global__ __launch_bounds__(256)
void hmma_kernel(int a0sel, const float* __restrict__ a0ext, int a0off, int lda0,
                 const float* __restrict__ W0, const float* __restrict__ W1,
                 const float* __restrict__ W2,
                 int nseg, int cps, int ldw,
                 int csel, int coff, int ldc, int M,
                 const float* __restrict__ bias,
                 const float* __restrict__ bng, const float* __restrict__ bnb)
{
    __shared__ __align__(16) __nv_bfloat16 Ah[128 * APAD];
    __shared__ __align__(16) __nv_bfloat16 Al[128 * APAD];
    __shared__ __align__(16) __nv_bfloat16 Bh[32 * BPAD];
    __shared__ __align__(16) __nv_bfloat16 Bl[32 * BPAD];

    const int tid = threadIdx.x;
    const int wid = tid >> 5;
    const int lane = tid & 31;
    const int bm = blockIdx.x * 128;
    const int bn = blockIdx.y * 128;
    const int mq = wid & 3;    // M quadrant (32 rows)
    const int nh = wid >> 2;   // N half (64 cols)

    float acc[2][8][4];
#pragma unroll
    for (int mi = 0; mi < 2; mi++)
#pragma unroll
        for (int ni = 0; ni < 8; ni++)
#pragma unroll
            for (int q = 0; q < 4; q++) acc[mi][ni][q] = 0.f;

    const float* Aseg[3] = { resolve_c(a0sel, a0ext, a0off), g_t1, g_t2 };
    const int ldA[3] = { lda0, 256, 256 };
    const float* Wseg[3] = { W0, W1, W2 };

    const uint32_t AhB = smem_u32(Ah);
    const uint32_t AlB = smem_u32(Al);
    const uint32_t BhB = smem_u32(Bh);
    const uint32_t BlB = smem_u32(Bl);

    // ldmatrix lane addressing (constant across chunks)
    const int a_m = (lane & 15);                 // row within 16-row tile
    const int a_k = ((lane >> 4) << 3);          // 0 or 8
    const int b_k = (lane & 15);                 // row within 16 k's

    const int nchunks = nseg * cps;
    for (int ch = 0; ch < nchunks; ch++) {
        const int s = ch / cps;
        const int kk = (ch % cps) * 32;
        const float* A = Aseg[s];
        const int lda = ldA[s];
        const float* W = Wseg[s];

        // ---- stage A: 128 rows x 32 k (bf16 hi/lo) ----
        {
            const int r = tid >> 1;
            const int k0 = (tid & 1) * 16;
            int gr = bm + r; gr = (gr < M) ? gr : (M - 1);
            const float4* src = (const float4*)(A + (size_t)gr * lda + kk + k0);
#pragma unroll
            for (int q = 0; q < 4; q++) {
                const float4 v = src[q];
                __nv_bfloat16 h0, l0, h1, l1, h2, l2, h3, l3;
                split_bf16(v.x, h0, l0); split_bf16(v.y, h1, l1);
                split_bf16(v.z, h2, l2); split_bf16(v.w, h3, l3);
                const int o = r * APAD + k0 + q * 4;
                *(uint2*)&Ah[o] = make_uint2(
                    ((uint32_t)*(uint16_t*)&h1 << 16) | *(uint16_t*)&h0,
                    ((uint32_t)*(uint16_t*)&h3 << 16) | *(uint16_t*)&h2);
                *(uint2*)&Al[o] = make_uint2(
                    ((uint32_t)*(uint16_t*)&l1 << 16) | *(uint16_t*)&l0,
                    ((uint32_t)*(uint16_t*)&l3 << 16) | *(uint16_t*)&l2);
            }
        }
        // ---- stage B: 32 k-rows x 128 n (natural [k][n]; ldmatrix.trans does the T) ----
        {
            const int k = tid >> 3;
            const int n0 = (tid & 7) * 16;
            const float4* src = (const float4*)(W + (size_t)(kk + k) * ldw + bn + n0);
#pragma unroll
            for (int q = 0; q < 4; q++) {
                const float4 v = src[q];
                __nv_bfloat16 h0, l0, h1, l1, h2, l2, h3, l3;
                split_bf16(v.x, h0, l0); split_bf16(v.y, h1, l1);
                split_bf16(v.z, h2, l2); split_bf16(v.w, h3, l3);
                const int o = k * BPAD + n0 + q * 4;
                *(uint2*)&Bh[o] = make_uint2(
                    ((uint32_t)*(uint16_t*)&h1 << 16) | *(uint16_t*)&h0,
                    ((uint32_t)*(uint16_t*)&h3 << 16) | *(uint16_t*)&h2);
                *(uint2*)&Bl[o] = make_uint2(
                    ((uint32_t)*(uint16_t*)&l1 << 16) | *(uint16_t*)&l0,
                    ((uint32_t)*(uint16_t*)&l3 << 16) | *(uint16_t*)&l2);
            }
        }
        __syncthreads();

        // ---- MMA: 2 k-steps of 16 ----
#pragma unroll
        for (int ks = 0; ks < 32; ks += 16) {
            uint32_t ahi[2][4], alo[2][4];
#pragma unroll
            for (int mi = 0; mi < 2; mi++) {
                const int m = mq * 32 + mi * 16 + a_m;
                const uint32_t off = (uint32_t)(m * APAD + ks + a_k) * 2;
                ldm_x4(ahi[mi], AhB + off);
                ldm_x4(alo[mi], AlB + off);
            }
            uint32_t bhi[8][2], blo[8][2];
#pragma unroll
            for (int ni = 0; ni < 8; ni++) {
                const uint32_t off =
                    (uint32_t)((ks + b_k) * BPAD + nh * 64 + ni * 8) * 2;
                ldm_x2t(bhi[ni], BhB + off);
                ldm_x2t(blo[ni], BlB + off);
            }
#pragma unroll
            for (int ni = 0; ni < 8; ni++)
#pragma unroll
                for (int mi = 0; mi < 2; mi++) {
                    mma16816(acc[mi][ni], ahi[mi], bhi[ni]);
                    mma16816(acc[mi][ni], ahi[mi], blo[ni]);
                    mma16816(acc[mi][ni], alo[mi], bhi[ni]);
                }
        }
        __syncthreads();
    }

    // ---- epilogue ----
    float* C = resolve_w(csel, coff);
    const float inv = rsqrtf(1.0f + 1e-5f);
    const int r0b = bm + mq * 32 + (lane >> 2);
    const int cb = bn + nh * 64 + (lane & 3) * 2;
#pragma unroll
    for (int ni = 0; ni < 8; ni++) {
        const int col = cb + ni * 8;
        float b0 = 0.f, b1 = 0.f, s0 = 1.f, s1 = 1.f, o0 = 0.f, o1 = 0.f;
        if (EPI == 1) {
            b0 = __ldg(bias + col); b1 = __ldg(bias + col + 1);
            s0 = __ldg(bng + col) * inv; s1 = __ldg(bng + col + 1) * inv;
            o0 = __ldg(bnb + col); o1 = __ldg(bnb + col + 1);
        }
#pragma unroll
        for (int mi = 0; mi < 2; mi++) {
#pragma unroll
            for (int half = 0; half < 2; half++) {
                const int r = r0b + mi * 16 + half * 8;
                if (r < M) {
                    float x0 = acc[mi][ni][half * 2 + 0];
                    float x1 = acc[mi][ni][half * 2 + 1];
                    if (EPI == 1) {
                        x0 = fmaxf(x0 + b0, 0.f) * s0 + o0;
                        x1 = fmaxf(x1 + b1, 0.f) * s1 + o1;
                    } else {
                        x0 = fmaxf(x0, 0.f);
                        x1 = fmaxf(x1, 0.f);
                    }
                    *(float2*)(C + (size_t)r * ldc + col) = make_float2(x0, x1);
                }
            }
        }
    }
}

// ---------------- fused edge encoder (FFMA2; unchanged, passing) ----------------
__global__ __launch_bounds__(256)
void edge_encoder_kernel(const float* __restrict__ edgenet,
                         const float* __restrict__ W1, const float* __restrict__ b1,
                         const float* __restrict__ gam, const float* __restrict__ bet,
                         const float* __restrict__ W2, const float* __restrict__ b2,
                         float* __restrict__ ew)
{
    __shared__ float xbuf[8][128];
    __shared__ float mbuf[8][512];
    const int w = threadIdx.x >> 5;
    const int lane = threadIdx.x & 31;
    const int warpGlobal = blockIdx.x * 8 + w;
    const int nWarps = gridDim.x * 8;
    const float inv = rsqrtf(1.0f + 1e-5f);

    const float4 b1v = *(const float4*)(b1 + lane * 4);
    const float4 g4  = *(const float4*)(gam + lane * 4);
    const float4 be4 = *(const float4*)(bet + lane * 4);
    const float4 b2v = *(const float4*)(b2 + lane * 4);
    const float sc[4] = {g4.x * inv, g4.y * inv, g4.z * inv, g4.w * inv};
    const float of[4] = {be4.x, be4.y, be4.z, be4.w};
    const float bb1[4] = {b1v.x, b1v.y, b1v.z, b1v.w};
    const float bb2[4] = {b2v.x, b2v.y, b2v.z, b2v.w};

    for (int e0 = warpGlobal * 4; e0 < EE; e0 += nWarps * 4) {
        float h[2][4][4];
#pragma unroll
        for (int half = 0; half < 2; half++) {
#pragma unroll
            for (int j = 0; j < 4; j++)
                xbuf[w][j * 32 + lane] = edgenet[(size_t)(e0 + j) * 64 + half * 32 + lane];
            __syncwarp();

            unsigned long long acc[4][2];
#pragma unroll
            for (int j = 0; j < 4; j++) { acc[j][0] = 0ULL; acc[j][1] = 0ULL; }
#pragma unroll 4
            for (int k = 0; k < 32; k++) {
                const float4 w4 = *(const float4*)(W1 + k * 128 + lane * 4);
                const unsigned long long wp0 = pk2p(w4.x, w4.y);
                const unsigned long long wp1 = pk2p(w4.z, w4.w);
#pragma unroll
                for (int j = 0; j < 4; j++) {
                    const unsigned long long xs = pk2(xbuf[w][j * 32 + k]);
                    ffma2(acc[j][0], xs, wp0);
                    ffma2(acc[j][1], xs, wp1);
                }
            }
            __syncwarp();
#pragma unroll
            for (int j = 0; j < 4; j++) {
                const float2 u0 = upk2(acc[j][0]);
                const float2 u1 = upk2(acc[j][1]);
                const float v[4] = {u0.x, u0.y, u1.x, u1.y};
#pragma unroll
                for (int c = 0; c < 4; c++)
                    mbuf[w][j * 128 + lane * 4 + c] =
                        fmaxf(v[c] + bb1[c], 0.f) * sc[c] + of[c];
            }
            __syncwarp();

            unsigned long long a2[4][2];
#pragma unroll
            for (int j = 0; j < 4; j++) { a2[j][0] = 0ULL; a2[j][1] = 0ULL; }
#pragma unroll 4
            for (int k = 0; k < 128; k++) {
                const float4 w4 = *(const float4*)(W2 + k * 128 + lane * 4);
                const unsigned long long wp0 = pk2p(w4.x, w4.y);
                const unsigned long long wp1 = pk2p(w4.z, w4.w);
#pragma unroll
                for (int j = 0; j < 4; j++) {
                    const unsigned long long mv = pk2(mbuf[w][j * 128 + k]);
                    ffma2(a2[j][0], mv, wp0);
                    ffma2(a2[j][1], mv, wp1);
                }
            }
#pragma unroll
            for (int j = 0; j < 4; j++) {
                const float2 u0 = upk2(a2[j][0]);
                const float2 u1 = upk2(a2[j][1]);
                h[half][j][0] = u0.x + bb2[0];
                h[half][j][1] = u0.y + bb2[1];
                h[half][j][2] = u1.x + bb2[2];
                h[half][j][3] = u1.y + bb2[3];
            }
            __syncwarp();
        }

#pragma unroll
        for (int j = 0; j < 4; j++) {
            float s11 = 0.f, s22 = 0.f, s12 = 0.f;
#pragma unroll
            for (int c = 0; c < 4; c++) {
                s11 += h[0][j][c] * h[0][j][c];
                s22 += h[1][j][c] * h[1][j][c];
                s12 += h[0][j][c] * h[1][j][c];
            }
#pragma unroll
            for (int off = 16; off > 0; off >>= 1) {
                s11 += __shfl_xor_sync(0xffffffffu, s11, off);
                s22 += __shfl_xor_sync(0xffffffffu, s22, off);
                s12 += __shfl_xor_sync(0xffffffffu, s12, off);
            }
            if (lane == 0) {
                const float n1 = fmaxf(sqrtf(s11), 1e-8f);
                const float n2 = fmaxf(sqrtf(s22), 1e-8f);
                ew[e0 + j] = (s12 / (n1 * n2) + 1.f) * 0.5f;
            }
        }
    }
}

// ---------------- CSR build ----------------
__global__ void degcnt_kernel(const void* __restrict__ ei, const float* __restrict__ ew)
{
    const int e = blockIdx.x * blockDim.x + threadIdx.x;
    if (e < EE) {
        const int row = idx_at(ei, e);
        const int col = idx_at(ei, e + EE);
        atomicAdd(&g_deg[row], ew[e]);
        atomicAdd(&g_cnt[col], 1);
    }
}

__global__ void dis_kernel()
{
    const int n = blockIdx.x * blockDim.x + threadIdx.x;
    if (n < NN) {
        const float d = g_deg[n];
        g_dis[n] = (d > 0.f) ? rsqrtf(fmaxf(d, 1e-30f)) : 0.f;
    }
}

__global__ void scan_kernel()
{
    __shared__ int sm[1024];
    __shared__ int carry;
    const int tid = threadIdx.x;
    if (tid == 0) carry = 0;
    __syncthreads();
    for (int base = 0; base < NN; base += 1024) {
        const int idx = base + tid;
        const int v = (idx < NN) ? g_cnt[idx] : 0;
        sm[tid] = v;
        __syncthreads();
        for (int off = 1; off < 1024; off <<= 1) {
            const int t = (tid >= off) ? sm[tid - off] : 0;
            __syncthreads();
            sm[tid] += t;
            __syncthreads();
        }
        const int c = carry;
        if (idx < NN) g_starts[idx] = c + sm[tid] - v;
        const int tot = sm[1023];
        __syncthreads();
        if (tid == 0) carry = c + tot;
        __syncthreads();
    }
    if (tid == 0) g_starts[NN] = carry;
}

__global__ void fill_kernel(const void* __restrict__ ei, const float* __restrict__ ew)
{
    const int e = blockIdx.x * blockDim.x + threadIdx.x;
    if (e < EE) {
        const int row = idx_at(ei, e);
        const int col = idx_at(ei, e + EE);
        const int p = g_starts[col] + atomicAdd(&g_cur[col], 1);
        g_srcA[p] = row;
        g_wA[p] = -g_dis[row] * ew[e] * g_dis[col];
    }
}

// ---------------- sparse propagation ----------------
__global__ __launch_bounds__(64)
void prop_kernel(int xsel, const float* __restrict__ xext, int xoff, int ldx,
                 int x0sel, const float* __restrict__ x0ext, int x0off, int ldx0,
                 int osel, int mode)
{
    const float* X  = resolve_c(xsel, xext, xoff);
    const float* X0 = (mode ? resolve_c(x0sel, x0ext, x0off) : nullptr);
    float* out = resolve_w(osel, 0);
    const int n = blockIdx.x;
    const int t = threadIdx.x;
    const int s0 = g_starts[n];
    const int s1 = g_starts[n + 1];
    float4 a = make_float4(0, 0, 0, 0);
    float4 b = make_float4(0, 0, 0, 0);
    int i = s0;
    for (; i + 1 < s1; i += 2) {
        const float w0 = g_wA[i];
        const float w1 = g_wA[i + 1];
        const int r0 = g_srcA[i];
        const int r1 = g_srcA[i + 1];
        const float4 x0 = *(const float4*)(X + (size_t)r0 * ldx + (t << 2));
        const float4 x1 = *(const float4*)(X + (size_t)r1 * ldx + (t << 2));
        a.x += w0 * x0.x; a.y += w0 * x0.y; a.z += w0 * x0.z; a.w += w0 * x0.w;
        b.x += w1 * x1.x; b.y += w1 * x1.y; b.z += w1 * x1.z; b.w += w1 * x1.w;
    }
    if (i < s1) {
        const float w0 = g_wA[i];
        const int r0 = g_srcA[i];
        const float4 x0 = *(const float4*)(X + (size_t)r0 * ldx + (t << 2));
        a.x += w0 * x0.x; a.y += w0 * x0.y; a.z += w0 * x0.z; a.w += w0 * x0.w;
    }
    float4 r = make_float4(a.x + b.x, a.y + b.y, a.z + b.z, a.w + b.w);
    if (mode) {
        const float4 xv = *(const float4*)(X0 + (size_t)n * ldx0 + (t << 2));
        r.x = 2.f * r.x - xv.x;
        r.y = 2.f * r.y - xv.y;
        r.z = 2.f * r.z - xv.z;
        r.w = 2.f * r.w - xv.w;
    }
    *(float4*)(out + (size_t)n * 256 + (t << 2)) = r;
}

// ---------------- final tiny GEMM: logit = z @ cls_w2 + b2 ----------------
__global__ void logits_kernel(const float* __restrict__ w2, const float* __restrict__ b2,
                              float* __restrict__ out)
{
    const int n = blockIdx.x * 8 + (threadIdx.x >> 5);
    const int lane = threadIdx.x & 31;
    if (n >= NN) return;
    float a0 = 0.f, a1 = 0.f;
    const float* z = g_z + (size_t)n * 256;
    for (int i = lane; i < 256; i += 32) {
        const float zv = z[i];
        a0 += zv * w2[2 * i];
        a1 += zv * w2[2 * i + 1];
    }
#pragma unroll
    for (int off = 16; off > 0; off >>= 1) {
        a0 += __shfl_xor_sync(0xffffffffu, a0, off);
        a1 += __shfl_xor_sync(0xffffffffu, a1, off);
    }
    if (lane == 0) {
        out[2 * n] = a0 + b2[0];
        out[2 * n + 1] = a1 + b2[1];
    }
}

// ---------------- launch ----------------
extern "C" void kernel_launch(void* const* d_in, const int* in_sizes, int n_in,
                              void* d_out, int out_size)
{
    (void)in_sizes; (void)n_in; (void)out_size;
    const float* features = (const float*)d_in[0];
    const void*  ei       = d_in[1];
    const float* edgenet  = (const float*)d_in[2];
    const float* cheb     = (const float*)d_in[3];
    const float* en_w1    = (const float*)d_in[4];
    const float* en_b1    = (const float*)d_in[5];
    const float* en_g1    = (const float*)d_in[6];
    const float* en_be1   = (const float*)d_in[7];
    const float* en_w2    = (const float*)d_in[8];
    const float* en_b2    = (const float*)d_in[9];
    const float* cls_w1   = (const float*)d_in[10];
    const float* cls_b1   = (const float*)d_in[11];
    const float* cls_g    = (const float*)d_in[12];
    const float* cls_b    = (const float*)d_in[13];
    const float* cls_w2   = (const float*)d_in[14];
    const float* cls_b2   = (const float*)d_in[15];
    float* out = (float*)d_out;
    float* ew  = out + NN * 2;

    detect_kernel<<<1, 32>>>(ei);
    zero_kernel<<<(NN + 255) / 256, 256>>>();

    edge_encoder_kernel<<<296, 256>>>(edgenet, en_w1, en_b1, en_g1, en_be1,
                                      en_w2, en_b2, ew);

    degcnt_kernel<<<(EE + 255) / 256, 256>>>(ei, ew);
    dis_kernel<<<(NN + 255) / 256, 256>>>();
    scan_kernel<<<1, 1024>>>();
    fill_kernel<<<(EE + 255) / 256, 256>>>(ei, ew);

    const int mtiles = (NN + 127) / 128;
    for (int l = 0; l < 4; l++) {
        const int xsel = (l == 0) ? SEL_EXT : SEL_JK;
        const int xoff = (l == 0) ? 0 : (l - 1) * 256;
        const int ldx  = (l == 0) ? 256 : 1024;
        prop_kernel<<<NN, 64>>>(xsel, features, xoff, ldx,
                                0, nullptr, 0, 0, SEL_T1, 0);
        prop_kernel<<<NN, 64>>>(SEL_T1, nullptr, 0, 256,
                                xsel, features, xoff, ldx, SEL_T2, 1);
        const float* B0 = cheb + (size_t)(l * 3 + 0) * 256 * 256;
        const float* B1 = cheb + (size_t)(l * 3 + 1) * 256 * 256;
        const float* B2 = cheb + (size_t)(l * 3 + 2) * 256 * 256;
        dim3 gC(mtiles, 2);
        hmma_kernel<2><<<gC, 256>>>(
            xsel, features, xoff, ldx,
            B0, B1, B2, 3, 8, 256,
            SEL_JK, l * 256, 1024, NN,
            nullptr, nullptr, nullptr);
    }

    dim3 gZ(mtiles, 2);
    hmma_kernel<1><<<gZ, 256>>>(
        SEL_JK, nullptr, 0, 1024,
        cls_w1, nullptr, nullptr, 1, 32, 256,
        SEL_Z, 0, 256, NN,
        cls_b1, cls_g, cls_b);
    logits_kernel<<<NN / 8, 256>>>(cls_w2, cls_b2, out);
}

// round 7
// speedup vs baseline: 1.7200x; 1.4458x over previous
#include <cuda_runtime.h>
#include <cuda_bf16.h>
#include <math.h>
#include <stdint.h>

#define NN 20000
#define EE 400000

// ---------------- mma.sync / ldmatrix helpers (baseline PTX, ok on compute_103) ------
__device__ __forceinline__ uint32_t smem_u32(const void* p) {
    uint32_t a;
    asm("{ .reg .u64 t; cvta.to.shared.u64 t, %1; cvt.u32.u64 %0, t; }" : "=r"(a) : "l"(p));
    return a;
}
__device__ __forceinline__ void ldm_x4(uint32_t* r, uint32_t addr) {
    asm volatile("ldmatrix.sync.aligned.m8n8.x4.shared.b16 {%0,%1,%2,%3}, [%4];"
                 : "=r"(r[0]), "=r"(r[1]), "=r"(r[2]), "=r"(r[3]) : "r"(addr));
}
__device__ __forceinline__ void ldm_x2t(uint32_t* r, uint32_t addr) {
    asm volatile("ldmatrix.sync.aligned.m8n8.x2.trans.shared.b16 {%0,%1}, [%2];"
                 : "=r"(r[0]), "=r"(r[1]) : "r"(addr));
}
__device__ __forceinline__ void mma16816(float* c, const uint32_t* a, const uint32_t* b) {
    asm volatile(
        "mma.sync.aligned.m16n8k16.row.col.f32.bf16.bf16.f32 "
        "{%0,%1,%2,%3}, {%4,%5,%6,%7}, {%8,%9}, {%0,%1,%2,%3};"
        : "+f"(c[0]), "+f"(c[1]), "+f"(c[2]), "+f"(c[3])
        : "r"(a[0]), "r"(a[1]), "r"(a[2]), "r"(a[3]), "r"(b[0]), "r"(b[1]));
}
__device__ __forceinline__ void split_bf16(float v, __nv_bfloat16& h, __nv_bfloat16& l) {
    h = __float2bfloat16(v);
    l = __float2bfloat16(v - __bfloat162float(h));
}
__device__ __forceinline__ uint32_t bfpack(__nv_bfloat16 a, __nv_bfloat16 b) {
    return ((uint32_t)*(uint16_t*)&b << 16) | (uint32_t)*(uint16_t*)&a;
}

// ---------------- scratch ----------------
#define CLS_OFF  786432
#define ENW1_OFF 1048576
#define ENW2_OFF 1052672
#define WTOTAL   1069056

__device__ float g_t1[(size_t)NN * 256];
__device__ float g_t2[(size_t)NN * 256];
__device__ float g_jk[(size_t)NN * 1024];
__device__ float g_z[(size_t)NN * 256];
__device__ float g_deg[NN];
__device__ float g_dis[NN];
__device__ int   g_cnt[NN];
__device__ int   g_cur[NN];
__device__ int   g_starts[NN + 1];
__device__ int   g_srcA[EE];
__device__ float g_wA[EE];
__device__ int   g_is64;
__device__ __nv_bfloat16 g_wsh[WTOTAL];
__device__ __nv_bfloat16 g_wsl[WTOTAL];

#define SEL_EXT 0
#define SEL_T1  1
#define SEL_T2  2
#define SEL_JK  3
#define SEL_Z   4

__device__ __forceinline__ const float* resolve_c(int sel, const float* ext, int off) {
    const float* p;
    switch (sel) {
        case SEL_T1: p = g_t1; break;
        case SEL_T2: p = g_t2; break;
        case SEL_JK: p = g_jk; break;
        case SEL_Z:  p = g_z;  break;
        default:     p = ext;  break;
    }
    return p + off;
}
__device__ __forceinline__ float* resolve_w(int sel, int off) {
    float* p;
    switch (sel) {
        case SEL_T1: p = g_t1; break;
        case SEL_T2: p = g_t2; break;
        case SEL_JK: p = g_jk; break;
        default:     p = g_z;  break;
    }
    return p + off;
}
__device__ __forceinline__ int idx_at(const void* ei, int i) {
    if (g_is64) return (int)((const long long*)ei)[i];
    return ((const int*)ei)[i];
}

__global__ void detect_kernel(const void* ei) {
    if (threadIdx.x == 0 && blockIdx.x == 0) {
        const long long* p = (const long long*)ei;
        int ok = 1;
        for (int i = 0; i < 64; i++) {
            long long v = p[i];
            if (v < 0 || v >= NN) ok = 0;
        }
        g_is64 = ok;
    }
}

__global__ void zero_kernel() {
    int n = blockIdx.x * blockDim.x + threadIdx.x;
    if (n < NN) { g_deg[n] = 0.f; g_cnt[n] = 0; g_cur[n] = 0; }
}

// ---------------- pre-split all weights to bf16 hi/lo ----------------
__global__ void split_weights_kernel(const float* __restrict__ cheb,
                                     const float* __restrict__ cls_w1,
                                     const float* __restrict__ en_w1,
                                     const float* __restrict__ en_w2)
{
    const int i = blockIdx.x * blockDim.x + threadIdx.x;
    if (i >= WTOTAL) return;
    float v;
    if (i < CLS_OFF) v = cheb[i];
    else if (i < ENW1_OFF) v = cls_w1[i - CLS_OFF];
    else if (i < ENW2_OFF) v = en_w1[i - ENW1_OFF];
    else v = en_w2[i - ENW2_OFF];
    __nv_bfloat16 h, l;
    split_bf16(v, h, l);
    g_wsh[i] = h;
    g_wsl[i] = l;
}

// ================= split-bf16 HMMA GEMM for node-side matrices ==================
// C[M, 256] = epi( sum_s A_s[M, K] @ W_s[K, 256] ); tile 128x128; K-chunk 32.
#define APAD 40
#define BPAD 136

template <int EPI>
__global__ __launch_bounds__(256)
void hmma_kernel(int a0sel, const float* __restrict__ a0ext, int a0off, int lda0,
                 int w0off, int nseg, int cps, int ldw,
                 int csel, int coff, int ldc, int M,
                 const float* __restrict__ bias,
                 const float* __restrict__ bng, const float* __restrict__ bnb)
{
    __shared__ __align__(16) __nv_bfloat16 Ah[128 * APAD];
    __shared__ __align__(16) __nv_bfloat16 Al[128 * APAD];
    __shared__ __align__(16) __nv_bfloat16 Bh[32 * BPAD];
    __shared__ __align__(16) __nv_bfloat16 Bl[32 * BPAD];

    const int tid = threadIdx.x;
    const int wid = tid >> 5;
    const int lane = tid & 31;
    const int bm = blockIdx.x * 128;
    const int bn = blockIdx.y * 128;
    const int mq = wid & 3;
    const int nh = wid >> 2;

    float acc[2][8][4];
#pragma unroll
    for (int mi = 0; mi < 2; mi++)
#pragma unroll
        for (int ni = 0; ni < 8; ni++)
#pragma unroll
            for (int q = 0; q < 4; q++) acc[mi][ni][q] = 0.f;

    const float* Aseg[3] = { resolve_c(a0sel, a0ext, a0off), g_t1, g_t2 };
    const int ldA[3] = { lda0, 256, 256 };

    const uint32_t AhB = smem_u32(Ah);
    const uint32_t AlB = smem_u32(Al);
    const uint32_t BhB = smem_u32(Bh);
    const uint32_t BlB = smem_u32(Bl);

    const int a_m = (lane & 15);
    const int a_k = ((lane >> 4) << 3);
    const int b_k = (lane & 15);

    const int nchunks = nseg * cps;
    for (int ch = 0; ch < nchunks; ch++) {
        const int s = ch / cps;
        const int kk = (ch % cps) * 32;
        const float* A = Aseg[s];
        const int lda = ldA[s];

        // ---- stage A: 128 rows x 32 k (fp32 -> bf16 hi/lo) ----
        {
            const int r = tid >> 1;
            const int k0 = (tid & 1) * 16;
            int gr = bm + r; gr = (gr < M) ? gr : (M - 1);
            const float4* src = (const float4*)(A + (size_t)gr * lda + kk + k0);
#pragma unroll
            for (int q = 0; q < 4; q++) {
                const float4 v = src[q];
                __nv_bfloat16 h0, l0, h1, l1, h2, l2, h3, l3;
                split_bf16(v.x, h0, l0); split_bf16(v.y, h1, l1);
                split_bf16(v.z, h2, l2); split_bf16(v.w, h3, l3);
                const int o = r * APAD + k0 + q * 4;
                *(uint2*)&Ah[o] = make_uint2(bfpack(h0, h1), bfpack(h2, h3));
                *(uint2*)&Al[o] = make_uint2(bfpack(l0, l1), bfpack(l2, l3));
            }
        }
        // ---- stage B: pre-split bf16 copy ----
        {
            const int k = tid >> 3;
            const int n0 = (tid & 7) * 16;
            const size_t so = (size_t)w0off + (size_t)s * 65536 +
                              (size_t)(kk + k) * ldw + bn + n0;
            const int o = k * BPAD + n0;
            *(uint4*)&Bh[o] = *(const uint4*)(g_wsh + so);
            *(uint4*)&Bh[o + 8] = *(const uint4*)(g_wsh + so + 8);
            *(uint4*)&Bl[o] = *(const uint4*)(g_wsl + so);
            *(uint4*)&Bl[o + 8] = *(const uint4*)(g_wsl + so + 8);
        }
        __syncthreads();

#pragma unroll
        for (int ks = 0; ks < 32; ks += 16) {
            uint32_t ahi[2][4], alo[2][4];
#pragma unroll
            for (int mi = 0; mi < 2; mi++) {
                const int m = mq * 32 + mi * 16 + a_m;
                const uint32_t off = (uint32_t)(m * APAD + ks + a_k) * 2;
                ldm_x4(ahi[mi], AhB + off);
                ldm_x4(alo[mi], AlB + off);
            }
            uint32_t bhi[8][2], blo[8][2];
#pragma unroll
            for (int ni = 0; ni < 8; ni++) {
                const uint32_t off =
                    (uint32_t)((ks + b_k) * BPAD + nh * 64 + ni * 8) * 2;
                ldm_x2t(bhi[ni], BhB + off);
                ldm_x2t(blo[ni], BlB + off);
            }
#pragma unroll
            for (int ni = 0; ni < 8; ni++)
#pragma unroll
                for (int mi = 0; mi < 2; mi++) {
                    mma16816(acc[mi][ni], ahi[mi], bhi[ni]);
                    mma16816(acc[mi][ni], ahi[mi], blo[ni]);
                    mma16816(acc[mi][ni], alo[mi], bhi[ni]);
                }
        }
        __syncthreads();
    }

    float* C = resolve_w(csel, coff);
    const float inv = rsqrtf(1.0f + 1e-5f);
    const int r0b = bm + mq * 32 + (lane >> 2);
    const int cb = bn + nh * 64 + (lane & 3) * 2;
#pragma unroll
    for (int ni = 0; ni < 8; ni++) {
        const int col = cb + ni * 8;
        float b0 = 0.f, b1 = 0.f, s0 = 1.f, s1 = 1.f, o0 = 0.f, o1 = 0.f;
        if (EPI == 1) {
            b0 = __ldg(bias + col); b1 = __ldg(bias + col + 1);
            s0 = __ldg(bng + col) * inv; s1 = __ldg(bng + col + 1) * inv;
            o0 = __ldg(bnb + col); o1 = __ldg(bnb + col + 1);
        }
#pragma unroll
        for (int mi = 0; mi < 2; mi++) {
#pragma unroll
            for (int half = 0; half < 2; half++) {
                const int r = r0b + mi * 16 + half * 8;
                if (r < M) {
                    float x0 = acc[mi][ni][half * 2 + 0];
                    float x1 = acc[mi][ni][half * 2 + 1];
                    if (EPI == 1) {
                        x0 = fmaxf(x0 + b0, 0.f) * s0 + o0;
                        x1 = fmaxf(x1 + b1, 0.f) * s1 + o1;
                    } else {
                        x0 = fmaxf(x0, 0.f);
                        x1 = fmaxf(x1, 0.f);
                    }
                    *(float2*)(C + (size_t)r * ldc + col) = make_float2(x0, x1);
                }
            }
        }
    }
}

// ================= split-bf16 HMMA fused edge encoder ==================
// Per 64-edge tile: both halves through parser (GEMM 32->128, relu+BN, GEMM 128->128),
// then cosine -> edge weight. Persistent grid; weights staged once per CTA.
#define EAPAD 72
#define EBPAD 136
#define EMPAD 136
#define ETILES (EE / 64)
// dynamic smem layout (bytes)
#define EO_W1H 0
#define EO_W1L 8704
#define EO_W2H 17408
#define EO_W2L 52224
#define EO_MH  87040
#define EO_ML  104448
#define EO_XH  121856
#define EO_XL  131072
#define EO_B1  140288
#define EO_SC  140800
#define EO_OF  141312
#define EO_B2  141824
#define EO_RED 142336
#define ESMEM  143872

__global__ __launch_bounds__(256)
void edge_hmma_kernel(const float* __restrict__ edgenet,
                      const float* __restrict__ b1v, const float* __restrict__ gam,
                      const float* __restrict__ bet, const float* __restrict__ b2v,
                      float* __restrict__ ew)
{
    extern __shared__ char sm[];
    __nv_bfloat16* W1h = (__nv_bfloat16*)(sm + EO_W1H);
    __nv_bfloat16* W1l = (__nv_bfloat16*)(sm + EO_W1L);
    __nv_bfloat16* W2h = (__nv_bfloat16*)(sm + EO_W2H);
    __nv_bfloat16* W2l = (__nv_bfloat16*)(sm + EO_W2L);
    __nv_bfloat16* Mh  = (__nv_bfloat16*)(sm + EO_MH);
    __nv_bfloat16* Ml  = (__nv_bfloat16*)(sm + EO_ML);
    __nv_bfloat16* Xh  = (__nv_bfloat16*)(sm + EO_XH);
    __nv_bfloat16* Xl  = (__nv_bfloat16*)(sm + EO_XL);
    float* b1s = (float*)(sm + EO_B1);
    float* scs = (float*)(sm + EO_SC);
    float* ofs = (float*)(sm + EO_OF);
    float* b2s = (float*)(sm + EO_B2);
    float* red = (float*)(sm + EO_RED);   // [3][2][64] -> q*128 + nh*64 + row

    const int tid = threadIdx.x;
    const int wid = tid >> 5, lane = tid & 31;
    const int mq = wid & 3, nh = wid >> 2;
    const float inv = rsqrtf(1.f + 1e-5f);

    // stage weights (pre-split) + epilogue vectors
    {
        const int r = tid >> 3, c0 = (tid & 7) * 16;
        const size_t so = (size_t)ENW1_OFF + r * 128 + c0;
        const int o = r * EBPAD + c0;
        *(uint4*)&W1h[o] = *(const uint4*)(g_wsh + so);
        *(uint4*)&W1h[o + 8] = *(const uint4*)(g_wsh + so + 8);
        *(uint4*)&W1l[o] = *(const uint4*)(g_wsl + so);
        *(uint4*)&W1l[o + 8] = *(const uint4*)(g_wsl + so + 8);
    }
    {
        const int r = tid >> 1, c0 = (tid & 1) * 64;
        const size_t so = (size_t)ENW2_OFF + r * 128 + c0;
#pragma unroll
        for (int q = 0; q < 8; q++) {
            *(uint4*)&W2h[r * EBPAD + c0 + q * 8] = *(const uint4*)(g_wsh + so + q * 8);
            *(uint4*)&W2l[r * EBPAD + c0 + q * 8] = *(const uint4*)(g_wsl + so + q * 8);
        }
    }
    if (tid < 128) {
        b1s[tid] = b1v[tid];
        scs[tid] = gam[tid] * inv;
        ofs[tid] = bet[tid];
        b2s[tid] = b2v[tid];
    }
    __syncthreads();

    const uint32_t XhB = smem_u32(Xh), XlB = smem_u32(Xl);
    const uint32_t W1hB = smem_u32(W1h), W1lB = smem_u32(W1l);
    const uint32_t W2hB = smem_u32(W2h), W2lB = smem_u32(W2l);
    const uint32_t MhB = smem_u32(Mh), MlB = smem_u32(Ml);

    const int a_m = lane & 15, a_k = (lane >> 4) << 3;
    const int b_k = lane & 15;
    const int rr = lane >> 2;
    const int cb = nh * 64 + (lane & 3) * 2;

    for (int t = blockIdx.x; t < ETILES; t += gridDim.x) {
        // ---- stage x tile: 64 edges x 64 feats ----
        {
            const int r = tid >> 2, c0 = (tid & 3) * 16;
            const float4* src = (const float4*)(edgenet + (size_t)(t * 64 + r) * 64 + c0);
#pragma unroll
            for (int q = 0; q < 4; q++) {
                const float4 v = src[q];
                __nv_bfloat16 h0, l0, h1, l1, h2, l2, h3, l3;
                split_bf16(v.x, h0, l0); split_bf16(v.y, h1, l1);
                split_bf16(v.z, h2, l2); split_bf16(v.w, h3, l3);
                const int o = r * EAPAD + c0 + q * 4;
                *(uint2*)&Xh[o] = make_uint2(bfpack(h0, h1), bfpack(h2, h3));
                *(uint2*)&Xl[o] = make_uint2(bfpack(l0, l1), bfpack(l2, l3));
            }
        }
        __syncthreads();

        float hacc[2][8][4];
#pragma unroll
        for (int half = 0; half < 2; half++) {
            // ---- GEMM1: [64x32] @ W1[32x128] ----
            float macc[8][4];
#pragma unroll
            for (int ni = 0; ni < 8; ni++)
#pragma unroll
                for (int q = 0; q < 4; q++) macc[ni][q] = 0.f;
#pragma unroll
            for (int ks = 0; ks < 32; ks += 16) {
                uint32_t ah[4], al[4];
                const uint32_t aoff =
                    (uint32_t)((mq * 16 + a_m) * EAPAD + half * 32 + ks + a_k) * 2;
                ldm_x4(ah, XhB + aoff);
                ldm_x4(al, XlB + aoff);
#pragma unroll
                for (int ni = 0; ni < 8; ni++) {
                    uint32_t bh[2], bl[2];
                    const uint32_t boff =
                        (uint32_t)((ks + b_k) * EBPAD + nh * 64 + ni * 8) * 2;
                    ldm_x2t(bh, W1hB + boff);
                    ldm_x2t(bl, W1lB + boff);
                    mma16816(macc[ni], ah, bh);
                    mma16816(macc[ni], ah, bl);
                    mma16816(macc[ni], al, bh);
                }
            }
            // ---- mid epilogue -> smem (bf16 hi/lo) ----
            __syncthreads();   // previous GEMM2 reads of M are done
            {
                const int r0 = mq * 16 + rr;
#pragma unroll
                for (int ni = 0; ni < 8; ni++) {
                    const int col = cb + ni * 8;
                    const float s0 = scs[col], s1 = scs[col + 1];
                    const float bb0 = b1s[col], bb1 = b1s[col + 1];
                    const float o0 = ofs[col], o1 = ofs[col + 1];
                    const float v00 = fmaxf(macc[ni][0] + bb0, 0.f) * s0 + o0;
                    const float v01 = fmaxf(macc[ni][1] + bb1, 0.f) * s1 + o1;
                    const float v10 = fmaxf(macc[ni][2] + bb0, 0.f) * s0 + o0;
                    const float v11 = fmaxf(macc[ni][3] + bb1, 0.f) * s1 + o1;
                    __nv_bfloat16 h0, l0, h1, l1;
                    split_bf16(v00, h0, l0); split_bf16(v01, h1, l1);
                    *(uint32_t*)&Mh[r0 * EMPAD + col] = bfpack(h0, h1);
                    *(uint32_t*)&Ml[r0 * EMPAD + col] = bfpack(l0, l1);
                    split_bf16(v10, h0, l0); split_bf16(v11, h1, l1);
                    *(uint32_t*)&Mh[(r0 + 8) * EMPAD + col] = bfpack(h0, h1);
                    *(uint32_t*)&Ml[(r0 + 8) * EMPAD + col] = bfpack(l0, l1);
                }
            }
            __syncthreads();
            // ---- GEMM2: [64x128] @ W2[128x128] ----
#pragma unroll
            for (int ni = 0; ni < 8; ni++)
#pragma unroll
                for (int q = 0; q < 4; q++) hacc[half][ni][q] = 0.f;
#pragma unroll
            for (int ks = 0; ks < 128; ks += 16) {
                uint32_t ah[4], al[4];
                const uint32_t aoff = (uint32_t)((mq * 16 + a_m) * EMPAD + ks + a_k) * 2;
                ldm_x4(ah, MhB + aoff);
                ldm_x4(al, MlB + aoff);
#pragma unroll
                for (int ni = 0; ni < 8; ni++) {
                    uint32_t bh[2], bl[2];
                    const uint32_t boff =
                        (uint32_t)((ks + b_k) * EBPAD + nh * 64 + ni * 8) * 2;
                    ldm_x2t(bh, W2hB + boff);
                    ldm_x2t(bl, W2lB + boff);
                    mma16816(hacc[half][ni], ah, bh);
                    mma16816(hacc[half][ni], ah, bl);
                    mma16816(hacc[half][ni], al, bh);
                }
            }
        }

        // ---- cosine reduction ----
        float p11a = 0.f, p22a = 0.f, p12a = 0.f;   // row r0
        float p11b = 0.f, p22b = 0.f, p12b = 0.f;   // row r0+8
#pragma unroll
        for (int ni = 0; ni < 8; ni++) {
            const int col = cb + ni * 8;
#pragma unroll
            for (int q = 0; q < 2; q++) {
                const float bb = b2s[col + q];
                const float h0a = hacc[0][ni][q] + bb;
                const float h1a = hacc[1][ni][q] + bb;
                const float h0b = hacc[0][ni][q + 2] + bb;
                const float h1b = hacc[1][ni][q + 2] + bb;
                p11a += h0a * h0a; p22a += h1a * h1a; p12a += h0a * h1a;
                p11b += h0b * h0b; p22b += h1b * h1b; p12b += h0b * h1b;
            }
        }
#pragma unroll
        for (int m = 1; m <= 2; m <<= 1) {
            p11a += __shfl_xor_sync(0xffffffffu, p11a, m);
            p22a += __shfl_xor_sync(0xffffffffu, p22a, m);
            p12a += __shfl_xor_sync(0xffffffffu, p12a, m);
            p11b += __shfl_xor_sync(0xffffffffu, p11b, m);
            p22b += __shfl_xor_sync(0xffffffffu, p22b, m);
            p12b += __shfl_xor_sync(0xffffffffu, p12b, m);
        }
        if ((lane & 3) == 0) {
            const int r0 = mq * 16 + rr;
            red[0 * 128 + nh * 64 + r0] = p11a;
            red[1 * 128 + nh * 64 + r0] = p22a;
            red[2 * 128 + nh * 64 + r0] = p12a;
            red[0 * 128 + nh * 64 + r0 + 8] = p11b;
            red[1 * 128 + nh * 64 + r0 + 8] = p22b;
            red[2 * 128 + nh * 64 + r0 + 8] = p12b;
        }
        __syncthreads();
        if (tid < 64) {
            const float s11 = red[0 * 128 + tid] + red[0 * 128 + 64 + tid];
            const float s22 = red[1 * 128 + tid] + red[1 * 128 + 64 + tid];
            const float s12 = red[2 * 128 + tid] + red[2 * 128 + 64 + tid];
            const float n1 = fmaxf(sqrtf(s11), 1e-8f);
            const float n2 = fmaxf(sqrtf(s22), 1e-8f);
            ew[t * 64 + tid] = (s12 / (n1 * n2) + 1.f) * 0.5f;
        }
        __syncthreads();
    }
}

// ---------------- CSR build ----------------
__global__ void degcnt_kernel(const void* __restrict__ ei, const float* __restrict__ ew)
{
    const int e = blockIdx.x * blockDim.x + threadIdx.x;
    if (e < EE) {
        const int row = idx_at(ei, e);
        const int col = idx_at(ei, e + EE);
        atomicAdd(&g_deg[row], ew[e]);
        atomicAdd(&g_cnt[col], 1);
    }
}

__global__ void dis_kernel()
{
    const int n = blockIdx.x * blockDim.x + threadIdx.x;
    if (n < NN) {
        const float d = g_deg[n];
        g_dis[n] = (d > 0.f) ? rsqrtf(fmaxf(d, 1e-30f)) : 0.f;
    }
}

__global__ void scan_kernel()
{
    __shared__ int sm[1024];
    __shared__ int carry;
    const int tid = threadIdx.x;
    if (tid == 0) carry = 0;
    __syncthreads();
    for (int base = 0; base < NN; base += 1024) {
        const int idx = base + tid;
        const int v = (idx < NN) ? g_cnt[idx] : 0;
        sm[tid] = v;
        __syncthreads();
        for (int off = 1; off < 1024; off <<= 1) {
            const int t = (tid >= off) ? sm[tid - off] : 0;
            __syncthreads();
            sm[tid] += t;
            __syncthreads();
        }
        const int c = carry;
        if (idx < NN) g_starts[idx] = c + sm[tid] - v;
        const int tot = sm[1023];
        __syncthreads();
        if (tid == 0) carry = c + tot;
        __syncthreads();
    }
    if (tid == 0) g_starts[NN] = carry;
}

__global__ void fill_kernel(const void* __restrict__ ei, const float* __restrict__ ew)
{
    const int e = blockIdx.x * blockDim.x + threadIdx.x;
    if (e < EE) {
        const int row = idx_at(ei, e);
        const int col = idx_at(ei, e + EE);
        const int p = g_starts[col] + atomicAdd(&g_cur[col], 1);
        g_srcA[p] = row;
        g_wA[p] = -g_dis[row] * ew[e] * g_dis[col];
    }
}

// ---------------- sparse propagation ----------------
__global__ __launch_bounds__(64)
void prop_kernel(int xsel, const float* __restrict__ xext, int xoff, int ldx,
                 int x0sel, const float* __restrict__ x0ext, int x0off, int ldx0,
                 int osel, int mode)
{
    const float* X  = resolve_c(xsel, xext, xoff);
    const float* X0 = (mode ? resolve_c(x0sel, x0ext, x0off) : nullptr);
    float* out = resolve_w(osel, 0);
    const int n = blockIdx.x;
    const int t = threadIdx.x;
    const int s0 = g_starts[n];
    const int s1 = g_starts[n + 1];
    float4 a = make_float4(0, 0, 0, 0);
    float4 b = make_float4(0, 0, 0, 0);
    int i = s0;
    for (; i + 1 < s1; i += 2) {
        const float w0 = g_wA[i];
        const float w1 = g_wA[i + 1];
        const int r0 = g_srcA[i];
        const int r1 = g_srcA[i + 1];
        const float4 x0 = *(const float4*)(X + (size_t)r0 * ldx + (t << 2));
        const float4 x1 = *(const float4*)(X + (size_t)r1 * ldx + (t << 2));
        a.x += w0 * x0.x; a.y += w0 * x0.y; a.z += w0 * x0.z; a.w += w0 * x0.w;
        b.x += w1 * x1.x; b.y += w1 * x1.y; b.z += w1 * x1.z; b.w += w1 * x1.w;
    }
    if (i < s1) {
        const float w0 = g_wA[i];
        const int r0 = g_srcA[i];
        const float4 x0 = *(const float4*)(X + (size_t)r0 * ldx + (t << 2));
        a.x += w0 * x0.x; a.y += w0 * x0.y; a.z += w0 * x0.z; a.w += w0 * x0.w;
    }
    float4 r = make_float4(a.x + b.x, a.y + b.y, a.z + b.z, a.w + b.w);
    if (mode) {
        const float4 xv = *(const float4*)(X0 + (size_t)n * ldx0 + (t << 2));
        r.x = 2.f * r.x - xv.x;
        r.y = 2.f * r.y - xv.y;
        r.z = 2.f * r.z - xv.z;
        r.w = 2.f * r.w - xv.w;
    }
    *(float4*)(out + (size_t)n * 256 + (t << 2)) = r;
}

// ---------------- final tiny GEMM: logit = z @ cls_w2 + b2 ----------------
__global__ void logits_kernel(const float* __restrict__ w2, const float* __restrict__ b2,
                              float* __restrict__ out)
{
    const int n = blockIdx.x * 8 + (threadIdx.x >> 5);
    const int lane = threadIdx.x & 31;
    if (n >= NN) return;
    float a0 = 0.f, a1 = 0.f;
    const float* z = g_z + (size_t)n * 256;
    for (int i = lane; i < 256; i += 32) {
        const float zv = z[i];
        a0 += zv * w2[2 * i];
        a1 += zv * w2[2 * i + 1];
    }
#pragma unroll
    for (int off = 16; off > 0; off >>= 1) {
        a0 += __shfl_xor_sync(0xffffffffu, a0, off);
        a1 += __shfl_xor_sync(0xffffffffu, a1, off);
    }
    if (lane == 0) {
        out[2 * n] = a0 + b2[0];
        out[2 * n + 1] = a1 + b2[1];
    }
}

// ---------------- launch ----------------
extern "C" void kernel_launch(void* const* d_in, const int* in_sizes, int n_in,
                              void* d_out, int out_size)
{
    (void)in_sizes; (void)n_in; (void)out_size;
    const float* features = (const float*)d_in[0];
    const void*  ei       = d_in[1];
    const float* edgenet  = (const float*)d_in[2];
    const float* cheb     = (const float*)d_in[3];
    const float* en_w1    = (const float*)d_in[4];
    const float* en_b1    = (const float*)d_in[5];
    const float* en_g1    = (const float*)d_in[6];
    const float* en_be1   = (const float*)d_in[7];
    const float* en_w2    = (const float*)d_in[8];
    const float* en_b2    = (const float*)d_in[9];
    const float* cls_w1   = (const float*)d_in[10];
    const float* cls_b1   = (const float*)d_in[11];
    const float* cls_g    = (const float*)d_in[12];
    const float* cls_b    = (const float*)d_in[13];
    const float* cls_w2   = (const float*)d_in[14];
    const float* cls_b2   = (const float*)d_in[15];
    float* out = (float*)d_out;
    float* ew  = out + NN * 2;

    cudaFuncSetAttribute(edge_hmma_kernel,
                         cudaFuncAttributeMaxDynamicSharedMemorySize, ESMEM);

    detect_kernel<<<1, 32>>>(ei);
    zero_kernel<<<(NN + 255) / 256, 256>>>();
    split_weights_kernel<<<(WTOTAL + 255) / 256, 256>>>(cheb, cls_w1, en_w1, en_w2);

    edge_hmma_kernel<<<148, 256, ESMEM>>>(edgenet, en_b1, en_g1, en_be1, en_b2, ew);

    degcnt_kernel<<<(EE + 255) / 256, 256>>>(ei, ew);
    dis_kernel<<<(NN + 255) / 256, 256>>>();
    scan_kernel<<<1, 1024>>>();
    fill_kernel<<<(EE + 255) / 256, 256>>>(ei, ew);

    const int mtiles = (NN + 127) / 128;
    for (int l = 0; l < 4; l++) {
        const int xsel = (l == 0) ? SEL_EXT : SEL_JK;
        const int xoff = (l == 0) ? 0 : (l - 1) * 256;
        const int ldx  = (l == 0) ? 256 : 1024;
        prop_kernel<<<NN, 64>>>(xsel, features, xoff, ldx,
                                0, nullptr, 0, 0, SEL_T1, 0);
        prop_kernel<<<NN, 64>>>(SEL_T1, nullptr, 0, 256,
                                xsel, features, xoff, ldx, SEL_T2, 1);
        dim3 gC(mtiles, 2);
        hmma_kernel<2><<<gC, 256>>>(
            xsel, features, xoff, ldx,
            (l * 3) * 65536, 3, 8, 256,
            SEL_JK, l * 256, 1024, NN,
            nullptr, nullptr, nullptr);
    }

    dim3 gZ(mtiles, 2);
    hmma_kernel<1><<<gZ, 256>>>(
        SEL_JK, nullptr, 0, 1024,
        CLS_OFF, 1, 32, 256,
        SEL_Z, 0, 256, NN,
        cls_b1, cls_g, cls_b);
    logits_kernel<<<NN / 8, 256>>>(cls_w2, cls_b2, out);
}

// round 8
// speedup vs baseline: 1.7419x; 1.0127x over previous
#include <cuda_runtime.h>
#include <cuda_bf16.h>
#include <math.h>
#include <stdint.h>

#define NN 20000
#define EE 400000

// ---------------- mma.sync / ldmatrix helpers (baseline PTX, ok on compute_103) ------
__device__ __forceinline__ uint32_t smem_u32(const void* p) {
    uint32_t a;
    asm("{ .reg .u64 t; cvta.to.shared.u64 t, %1; cvt.u32.u64 %0, t; }" : "=r"(a) : "l"(p));
    return a;
}
__device__ __forceinline__ void ldm_x4(uint32_t* r, uint32_t addr) {
    asm volatile("ldmatrix.sync.aligned.m8n8.x4.shared.b16 {%0,%1,%2,%3}, [%4];"
                 : "=r"(r[0]), "=r"(r[1]), "=r"(r[2]), "=r"(r[3]) : "r"(addr));
}
// x4 trans: lanes 0-7: k0-7/n0-7, 8-15: k8-15/n0-7, 16-23: k0-7/n8-15, 24-31: k8-15/n8-15
// -> r[0],r[1] = b-frag for first n8;  r[2],r[3] = b-frag for second n8.
__device__ __forceinline__ void ldm_x4t(uint32_t* r, uint32_t addr) {
    asm volatile("ldmatrix.sync.aligned.m8n8.x4.trans.shared.b16 {%0,%1,%2,%3}, [%4];"
                 : "=r"(r[0]), "=r"(r[1]), "=r"(r[2]), "=r"(r[3]) : "r"(addr));
}
__device__ __forceinline__ void mma16816(float* c, const uint32_t* a, const uint32_t* b) {
    asm volatile(
        "mma.sync.aligned.m16n8k16.row.col.f32.bf16.bf16.f32 "
        "{%0,%1,%2,%3}, {%4,%5,%6,%7}, {%8,%9}, {%0,%1,%2,%3};"
        : "+f"(c[0]), "+f"(c[1]), "+f"(c[2]), "+f"(c[3])
        : "r"(a[0]), "r"(a[1]), "r"(a[2]), "r"(a[3]), "r"(b[0]), "r"(b[1]));
}
__device__ __forceinline__ void split_bf16(float v, __nv_bfloat16& h, __nv_bfloat16& l) {
    h = __float2bfloat16(v);
    l = __float2bfloat16(v - __bfloat162float(h));
}
__device__ __forceinline__ uint32_t bfpack(__nv_bfloat16 a, __nv_bfloat16 b) {
    return ((uint32_t)*(uint16_t*)&b << 16) | (uint32_t)*(uint16_t*)&a;
}

// ---------------- scratch ----------------
#define CLS_OFF  786432
#define ENW1_OFF 1048576
#define ENW2_OFF 1052672
#define WTOTAL   1069056

__device__ float g_t1[(size_t)NN * 256];
__device__ float g_t2[(size_t)NN * 256];
__device__ float g_jk[(size_t)NN * 1024];
__device__ float g_z[(size_t)NN * 256];
__device__ float g_deg[NN];
__device__ float g_dis[NN];
__device__ int   g_cnt[NN];
__device__ int   g_cur[NN];
__device__ int   g_starts[NN + 1];
__device__ int   g_srcA[EE];
__device__ float g_wA[EE];
__device__ int   g_is64;
__device__ __nv_bfloat16 g_wsh[WTOTAL];
__device__ __nv_bfloat16 g_wsl[WTOTAL];

#define SEL_EXT 0
#define SEL_T1  1
#define SEL_T2  2
#define SEL_JK  3
#define SEL_Z   4

__device__ __forceinline__ const float* resolve_c(int sel, const float* ext, int off) {
    const float* p;
    switch (sel) {
        case SEL_T1: p = g_t1; break;
        case SEL_T2: p = g_t2; break;
        case SEL_JK: p = g_jk; break;
        case SEL_Z:  p = g_z;  break;
        default:     p = ext;  break;
    }
    return p + off;
}
__device__ __forceinline__ float* resolve_w(int sel, int off) {
    float* p;
    switch (sel) {
        case SEL_T1: p = g_t1; break;
        case SEL_T2: p = g_t2; break;
        case SEL_JK: p = g_jk; break;
        default:     p = g_z;  break;
    }
    return p + off;
}
__device__ __forceinline__ int idx_at(const void* ei, int i) {
    if (g_is64) return (int)((const long long*)ei)[i];
    return ((const int*)ei)[i];
}

__global__ void detect_kernel(const void* ei) {
    if (threadIdx.x == 0 && blockIdx.x == 0) {
        const long long* p = (const long long*)ei;
        int ok = 1;
        for (int i = 0; i < 64; i++) {
            long long v = p[i];
            if (v < 0 || v >= NN) ok = 0;
        }
        g_is64 = ok;
    }
}

__global__ void zero_kernel() {
    int n = blockIdx.x * blockDim.x + threadIdx.x;
    if (n < NN) { g_deg[n] = 0.f; g_cnt[n] = 0; g_cur[n] = 0; }
}

// ---------------- pre-split all weights to bf16 hi/lo ----------------
__global__ void split_weights_kernel(const float* __restrict__ cheb,
                                     const float* __restrict__ cls_w1,
                                     const float* __restrict__ en_w1,
                                     const float* __restrict__ en_w2)
{
    const int i = blockIdx.x * blockDim.x + threadIdx.x;
    if (i >= WTOTAL) return;
    float v;
    if (i < CLS_OFF) v = cheb[i];
    else if (i < ENW1_OFF) v = cls_w1[i - CLS_OFF];
    else if (i < ENW2_OFF) v = en_w1[i - ENW1_OFF];
    else v = en_w2[i - ENW2_OFF];
    __nv_bfloat16 h, l;
    split_bf16(v, h, l);
    g_wsh[i] = h;
    g_wsl[i] = l;
}

// ================= split-bf16 HMMA GEMM for node-side matrices ==================
// C[M, 256] = epi( sum_s A_s[M, K] @ W_s[K, 256] ); tile 128x128; K-chunk 32.
// Double-buffered staging (dynamic smem), ldmatrix.x4.trans on the B side.
#define APAD 40
#define BPAD 136
#define HA_SZ (128 * APAD)  // 5120 bf16
#define HB_SZ (32 * BPAD)   // 4352 bf16
// dynamic smem layout (bf16 elems): Ah[2], Al[2], Bh[2], Bl[2]
#define D_AH(b) ((b) * HA_SZ)
#define D_AL(b) (2 * HA_SZ + (b) * HA_SZ)
#define D_BH(b) (4 * HA_SZ + (b) * HB_SZ)
#define D_BL(b) (4 * HA_SZ + 2 * HB_SZ + (b) * HB_SZ)
#define HSMEM ((4 * HA_SZ + 4 * HB_SZ) * 2)   // 75776 bytes

template <int EPI>
__global__ __launch_bounds__(256, 2)
void hmma_kernel(int a0sel, const float* __restrict__ a0ext, int a0off, int lda0,
                 int w0off, int nseg, int cps, int ldw,
                 int csel, int coff, int ldc, int M,
                 const float* __restrict__ bias,
                 const float* __restrict__ bng, const float* __restrict__ bnb)
{
    extern __shared__ __nv_bfloat16 dsm[];

    const int tid = threadIdx.x;
    const int wid = tid >> 5;
    const int lane = tid & 31;
    const int bm = blockIdx.x * 128;
    const int bn = blockIdx.y * 128;
    const int mq = wid & 3;
    const int nh = wid >> 2;

    float acc[2][8][4];
#pragma unroll
    for (int mi = 0; mi < 2; mi++)
#pragma unroll
        for (int ni = 0; ni < 8; ni++)
#pragma unroll
            for (int q = 0; q < 4; q++) acc[mi][ni][q] = 0.f;

    const float* Aseg[3] = { resolve_c(a0sel, a0ext, a0off), g_t1, g_t2 };
    const int ldA[3] = { lda0, 256, 256 };

    const uint32_t base = smem_u32(dsm);
    const int a_m = (lane & 15);
    const int a_k = ((lane >> 4) << 3);
    const int b_row = (lane & 15);
    const int b_col8 = ((lane >> 4) << 3);

    // staging thread mapping (constant)
    const int sa_r = tid >> 1;
    const int sa_k0 = (tid & 1) * 16;
    const int sb_k = tid >> 3;
    const int sb_n0 = (tid & 7) * 16;

    const int nchunks = nseg * cps;

    auto stage = [&](int ch, int buf) {
        const int s = ch / cps;
        const int kk = (ch % cps) * 32;
        const float* A = Aseg[s];
        const int lda = ldA[s];
        // A: 128 rows x 32 k (fp32 -> bf16 hi/lo)
        {
            int gr = bm + sa_r; gr = (gr < M) ? gr : (M - 1);
            const float4* src = (const float4*)(A + (size_t)gr * lda + kk + sa_k0);
            __nv_bfloat16* Ah = dsm + D_AH(buf);
            __nv_bfloat16* Al = dsm + D_AL(buf);
#pragma unroll
            for (int q = 0; q < 4; q++) {
                const float4 v = src[q];
                __nv_bfloat16 h0, l0, h1, l1, h2, l2, h3, l3;
                split_bf16(v.x, h0, l0); split_bf16(v.y, h1, l1);
                split_bf16(v.z, h2, l2); split_bf16(v.w, h3, l3);
                const int o = sa_r * APAD + sa_k0 + q * 4;
                *(uint2*)&Ah[o] = make_uint2(bfpack(h0, h1), bfpack(h2, h3));
                *(uint2*)&Al[o] = make_uint2(bfpack(l0, l1), bfpack(l2, l3));
            }
        }
        // B: pre-split bf16 copy
        {
            const size_t so = (size_t)w0off + (size_t)s * 65536 +
                              (size_t)(kk + sb_k) * ldw + bn + sb_n0;
            const int o = sb_k * BPAD + sb_n0;
            __nv_bfloat16* Bh = dsm + D_BH(buf);
            __nv_bfloat16* Bl = dsm + D_BL(buf);
            *(uint4*)&Bh[o] = *(const uint4*)(g_wsh + so);
            *(uint4*)&Bh[o + 8] = *(const uint4*)(g_wsh + so + 8);
            *(uint4*)&Bl[o] = *(const uint4*)(g_wsl + so);
            *(uint4*)&Bl[o + 8] = *(const uint4*)(g_wsl + so + 8);
        }
    };

    stage(0, 0);
    __syncthreads();

    for (int ch = 0; ch < nchunks; ch++) {
        const int cur = ch & 1;
        if (ch + 1 < nchunks) stage(ch + 1, cur ^ 1);

        const uint32_t AhB = base + D_AH(cur) * 2;
        const uint32_t AlB = base + D_AL(cur) * 2;
        const uint32_t BhB = base + D_BH(cur) * 2;
        const uint32_t BlB = base + D_BL(cur) * 2;

#pragma unroll
        for (int ks = 0; ks < 32; ks += 16) {
            uint32_t ahi[2][4], alo[2][4];
#pragma unroll
            for (int mi = 0; mi < 2; mi++) {
                const int m = mq * 32 + mi * 16 + a_m;
                const uint32_t off = (uint32_t)(m * APAD + ks + a_k) * 2;
                ldm_x4(ahi[mi], AhB + off);
                ldm_x4(alo[mi], AlB + off);
            }
#pragma unroll
            for (int nip = 0; nip < 4; nip++) {
                uint32_t bh4[4], bl4[4];
                const uint32_t off =
                    (uint32_t)((ks + b_row) * BPAD + nh * 64 + nip * 16 + b_col8) * 2;
                ldm_x4t(bh4, BhB + off);
                ldm_x4t(bl4, BlB + off);
#pragma unroll
                for (int half = 0; half < 2; half++) {
                    const int ni = nip * 2 + half;
#pragma unroll
                    for (int mi = 0; mi < 2; mi++) {
                        mma16816(acc[mi][ni], ahi[mi], bh4 + half * 2);
                        mma16816(acc[mi][ni], ahi[mi], bl4 + half * 2);
                        mma16816(acc[mi][ni], alo[mi], bh4 + half * 2);
                    }
                }
            }
        }
        __syncthreads();
    }

    float* C = resolve_w(csel, coff);
    const float inv = rsqrtf(1.0f + 1e-5f);
    const int r0b = bm + mq * 32 + (lane >> 2);
    const int cb = bn + nh * 64 + (lane & 3) * 2;
#pragma unroll
    for (int ni = 0; ni < 8; ni++) {
        const int col = cb + ni * 8;
        float b0 = 0.f, b1 = 0.f, s0 = 1.f, s1 = 1.f, o0 = 0.f, o1 = 0.f;
        if (EPI == 1) {
            b0 = __ldg(bias + col); b1 = __ldg(bias + col + 1);
            s0 = __ldg(bng + col) * inv; s1 = __ldg(bng + col + 1) * inv;
            o0 = __ldg(bnb + col); o1 = __ldg(bnb + col + 1);
        }
#pragma unroll
        for (int mi = 0; mi < 2; mi++) {
#pragma unroll
            for (int half = 0; half < 2; half++) {
                const int r = r0b + mi * 16 + half * 8;
                if (r < M) {
                    float x0 = acc[mi][ni][half * 2 + 0];
                    float x1 = acc[mi][ni][half * 2 + 1];
                    if (EPI == 1) {
                        x0 = fmaxf(x0 + b0, 0.f) * s0 + o0;
                        x1 = fmaxf(x1 + b1, 0.f) * s1 + o1;
                    } else {
                        x0 = fmaxf(x0, 0.f);
                        x1 = fmaxf(x1, 0.f);
                    }
                    *(float2*)(C + (size_t)r * ldc + col) = make_float2(x0, x1);
                }
            }
        }
    }
}

// ================= split-bf16 HMMA fused edge encoder ==================
#define EAPAD 72
#define EBPAD 136
#define EMPAD 136
#define ETILES (EE / 64)
#define EO_W1H 0
#define EO_W1L 8704
#define EO_W2H 17408
#define EO_W2L 52224
#define EO_MH  87040
#define EO_ML  104448
#define EO_XH  121856
#define EO_XL  131072
#define EO_B1  140288
#define EO_SC  140800
#define EO_OF  141312
#define EO_B2  141824
#define EO_RED 142336
#define ESMEM  143872

__global__ __launch_bounds__(256)
void edge_hmma_kernel(const float* __restrict__ edgenet,
                      const float* __restrict__ b1v, const float* __restrict__ gam,
                      const float* __restrict__ bet, const float* __restrict__ b2v,
                      float* __restrict__ ew)
{
    extern __shared__ char sm[];
    __nv_bfloat16* W1h = (__nv_bfloat16*)(sm + EO_W1H);
    __nv_bfloat16* W1l = (__nv_bfloat16*)(sm + EO_W1L);
    __nv_bfloat16* W2h = (__nv_bfloat16*)(sm + EO_W2H);
    __nv_bfloat16* W2l = (__nv_bfloat16*)(sm + EO_W2L);
    __nv_bfloat16* Mh  = (__nv_bfloat16*)(sm + EO_MH);
    __nv_bfloat16* Ml  = (__nv_bfloat16*)(sm + EO_ML);
    __nv_bfloat16* Xh  = (__nv_bfloat16*)(sm + EO_XH);
    __nv_bfloat16* Xl  = (__nv_bfloat16*)(sm + EO_XL);
    float* b1s = (float*)(sm + EO_B1);
    float* scs = (float*)(sm + EO_SC);
    float* ofs = (float*)(sm + EO_OF);
    float* b2s = (float*)(sm + EO_B2);
    float* red = (float*)(sm + EO_RED);

    const int tid = threadIdx.x;
    const int wid = tid >> 5, lane = tid & 31;
    const int mq = wid & 3, nh = wid >> 2;
    const float inv = rsqrtf(1.f + 1e-5f);

    {
        const int r = tid >> 3, c0 = (tid & 7) * 16;
        const size_t so = (size_t)ENW1_OFF + r * 128 + c0;
        const int o = r * EBPAD + c0;
        *(uint4*)&W1h[o] = *(const uint4*)(g_wsh + so);
        *(uint4*)&W1h[o + 8] = *(const uint4*)(g_wsh + so + 8);
        *(uint4*)&W1l[o] = *(const uint4*)(g_wsl + so);
        *(uint4*)&W1l[o + 8] = *(const uint4*)(g_wsl + so + 8);
    }
    {
        const int r = tid >> 1, c0 = (tid & 1) * 64;
        const size_t so = (size_t)ENW2_OFF + r * 128 + c0;
#pragma unroll
        for (int q = 0; q < 8; q++) {
            *(uint4*)&W2h[r * EBPAD + c0 + q * 8] = *(const uint4*)(g_wsh + so + q * 8);
            *(uint4*)&W2l[r * EBPAD + c0 + q * 8] = *(const uint4*)(g_wsl + so + q * 8);
        }
    }
    if (tid < 128) {
        b1s[tid] = b1v[tid];
        scs[tid] = gam[tid] * inv;
        ofs[tid] = bet[tid];
        b2s[tid] = b2v[tid];
    }
    __syncthreads();

    const uint32_t XhB = smem_u32(Xh), XlB = smem_u32(Xl);
    const uint32_t W1hB = smem_u32(W1h), W1lB = smem_u32(W1l);
    const uint32_t W2hB = smem_u32(W2h), W2lB = smem_u32(W2l);
    const uint32_t MhB = smem_u32(Mh), MlB = smem_u32(Ml);

    const int a_m = lane & 15, a_k = (lane >> 4) << 3;
    const int b_row = lane & 15, b_col8 = (lane >> 4) << 3;
    const int rr = lane >> 2;
    const int cb = nh * 64 + (lane & 3) * 2;

    for (int t = blockIdx.x; t < ETILES; t += gridDim.x) {
        {
            const int r = tid >> 2, c0 = (tid & 3) * 16;
            const float4* src = (const float4*)(edgenet + (size_t)(t * 64 + r) * 64 + c0);
#pragma unroll
            for (int q = 0; q < 4; q++) {
                const float4 v = src[q];
                __nv_bfloat16 h0, l0, h1, l1, h2, l2, h3, l3;
                split_bf16(v.x, h0, l0); split_bf16(v.y, h1, l1);
                split_bf16(v.z, h2, l2); split_bf16(v.w, h3, l3);
                const int o = r * EAPAD + c0 + q * 4;
                *(uint2*)&Xh[o] = make_uint2(bfpack(h0, h1), bfpack(h2, h3));
                *(uint2*)&Xl[o] = make_uint2(bfpack(l0, l1), bfpack(l2, l3));
            }
        }
        __syncthreads();

        float hacc[2][8][4];
#pragma unroll
        for (int half = 0; half < 2; half++) {
            float macc[8][4];
#pragma unroll
            for (int ni = 0; ni < 8; ni++)
#pragma unroll
                for (int q = 0; q < 4; q++) macc[ni][q] = 0.f;
#pragma unroll
            for (int ks = 0; ks < 32; ks += 16) {
                uint32_t ah[4], al[4];
                const uint32_t aoff =
                    (uint32_t)((mq * 16 + a_m) * EAPAD + half * 32 + ks + a_k) * 2;
                ldm_x4(ah, XhB + aoff);
                ldm_x4(al, XlB + aoff);
#pragma unroll
                for (int nip = 0; nip < 4; nip++) {
                    uint32_t bh4[4], bl4[4];
                    const uint32_t boff =
                        (uint32_t)((ks + b_row) * EBPAD + nh * 64 + nip * 16 + b_col8) * 2;
                    ldm_x4t(bh4, W1hB + boff);
                    ldm_x4t(bl4, W1lB + boff);
#pragma unroll
                    for (int hh = 0; hh < 2; hh++) {
                        const int ni = nip * 2 + hh;
                        mma16816(macc[ni], ah, bh4 + hh * 2);
                        mma16816(macc[ni], ah, bl4 + hh * 2);
                        mma16816(macc[ni], al, bh4 + hh * 2);
                    }
                }
            }
            __syncthreads();
            {
                const int r0 = mq * 16 + rr;
#pragma unroll
                for (int ni = 0; ni < 8; ni++) {
                    const int col = cb + ni * 8;
                    const float s0 = scs[col], s1 = scs[col + 1];
                    const float bb0 = b1s[col], bb1 = b1s[col + 1];
                    const float o0 = ofs[col], o1 = ofs[col + 1];
                    const float v00 = fmaxf(macc[ni][0] + bb0, 0.f) * s0 + o0;
                    const float v01 = fmaxf(macc[ni][1] + bb1, 0.f) * s1 + o1;
                    const float v10 = fmaxf(macc[ni][2] + bb0, 0.f) * s0 + o0;
                    const float v11 = fmaxf(macc[ni][3] + bb1, 0.f) * s1 + o1;
                    __nv_bfloat16 h0, l0, h1, l1;
                    split_bf16(v00, h0, l0); split_bf16(v01, h1, l1);
                    *(uint32_t*)&Mh[r0 * EMPAD + col] = bfpack(h0, h1);
                    *(uint32_t*)&Ml[r0 * EMPAD + col] = bfpack(l0, l1);
                    split_bf16(v10, h0, l0); split_bf16(v11, h1, l1);
                    *(uint32_t*)&Mh[(r0 + 8) * EMPAD + col] = bfpack(h0, h1);
                    *(uint32_t*)&Ml[(r0 + 8) * EMPAD + col] = bfpack(l0, l1);
                }
            }
            __syncthreads();
#pragma unroll
            for (int ni = 0; ni < 8; ni++)
#pragma unroll
                for (int q = 0; q < 4; q++) hacc[half][ni][q] = 0.f;
#pragma unroll
            for (int ks = 0; ks < 128; ks += 16) {
                uint32_t ah[4], al[4];
                const uint32_t aoff = (uint32_t)((mq * 16 + a_m) * EMPAD + ks + a_k) * 2;
                ldm_x4(ah, MhB + aoff);
                ldm_x4(al, MlB + aoff);
#pragma unroll
                for (int nip = 0; nip < 4; nip++) {
                    uint32_t bh4[4], bl4[4];
                    const uint32_t boff =
                        (uint32_t)((ks + b_row) * EBPAD + nh * 64 + nip * 16 + b_col8) * 2;
                    ldm_x4t(bh4, W2hB + boff);
                    ldm_x4t(bl4, W2lB + boff);
#pragma unroll
                    for (int hh = 0; hh < 2; hh++) {
                        const int ni = nip * 2 + hh;
                        mma16816(hacc[half][ni], ah, bh4 + hh * 2);
                        mma16816(hacc[half][ni], ah, bl4 + hh * 2);
                        mma16816(hacc[half][ni], al, bh4 + hh * 2);
                    }
                }
            }
        }

        float p11a = 0.f, p22a = 0.f, p12a = 0.f;
        float p11b = 0.f, p22b = 0.f, p12b = 0.f;
#pragma unroll
        for (int ni = 0; ni < 8; ni++) {
            const int col = cb + ni * 8;
#pragma unroll
            for (int q = 0; q < 2; q++) {
                const float bb = b2s[col + q];
                const float h0a = hacc[0][ni][q] + bb;
                const float h1a = hacc[1][ni][q] + bb;
                const float h0b = hacc[0][ni][q + 2] + bb;
                const float h1b = hacc[1][ni][q + 2] + bb;
                p11a += h0a * h0a; p22a += h1a * h1a; p12a += h0a * h1a;
                p11b += h0b * h0b; p22b += h1b * h1b; p12b += h0b * h1b;
            }
        }
#pragma unroll
        for (int m = 1; m <= 2; m <<= 1) {
            p11a += __shfl_xor_sync(0xffffffffu, p11a, m);
            p22a += __shfl_xor_sync(0xffffffffu, p22a, m);
            p12a += __shfl_xor_sync(0xffffffffu, p12a, m);
            p11b += __shfl_xor_sync(0xffffffffu, p11b, m);
            p22b += __shfl_xor_sync(0xffffffffu, p22b, m);
            p12b += __shfl_xor_sync(0xffffffffu, p12b, m);
        }
        if ((lane & 3) == 0) {
            const int r0 = mq * 16 + rr;
            red[0 * 128 + nh * 64 + r0] = p11a;
            red[1 * 128 + nh * 64 + r0] = p22a;
            red[2 * 128 + nh * 64 + r0] = p12a;
            red[0 * 128 + nh * 64 + r0 + 8] = p11b;
            red[1 * 128 + nh * 64 + r0 + 8] = p22b;
            red[2 * 128 + nh * 64 + r0 + 8] = p12b;
        }
        __syncthreads();
        if (tid < 64) {
            const float s11 = red[0 * 128 + tid] + red[0 * 128 + 64 + tid];
            const float s22 = red[1 * 128 + tid] + red[1 * 128 + 64 + tid];
            const float s12 = red[2 * 128 + tid] + red[2 * 128 + 64 + tid];
            const float n1 = fmaxf(sqrtf(s11), 1e-8f);
            const float n2 = fmaxf(sqrtf(s22), 1e-8f);
            ew[t * 64 + tid] = (s12 / (n1 * n2) + 1.f) * 0.5f;
        }
        __syncthreads();
    }
}

// ---------------- CSR build ----------------
__global__ void degcnt_kernel(const void* __restrict__ ei, const float* __restrict__ ew)
{
    const int e = blockIdx.x * blockDim.x + threadIdx.x;
    if (e < EE) {
        const int row = idx_at(ei, e);
        const int col = idx_at(ei, e + EE);
        atomicAdd(&g_deg[row], ew[e]);
        atomicAdd(&g_cnt[col], 1);
    }
}

__global__ void dis_kernel()
{
    const int n = blockIdx.x * blockDim.x + threadIdx.x;
    if (n < NN) {
        const float d = g_deg[n];
        g_dis[n] = (d > 0.f) ? rsqrtf(fmaxf(d, 1e-30f)) : 0.f;
    }
}

__global__ void scan_kernel()
{
    __shared__ int sm[1024];
    __shared__ int carry;
    const int tid = threadIdx.x;
    if (tid == 0) carry = 0;
    __syncthreads();
    for (int base = 0; base < NN; base += 1024) {
        const int idx = base + tid;
        const int v = (idx < NN) ? g_cnt[idx] : 0;
        sm[tid] = v;
        __syncthreads();
        for (int off = 1; off < 1024; off <<= 1) {
            const int t = (tid >= off) ? sm[tid - off] : 0;
            __syncthreads();
            sm[tid] += t;
            __syncthreads();
        }
        const int c = carry;
        if (idx < NN) g_starts[idx] = c + sm[tid] - v;
        const int tot = sm[1023];
        __syncthreads();
        if (tid == 0) carry = c + tot;
        __syncthreads();
    }
    if (tid == 0) g_starts[NN] = carry;
}

__global__ void fill_kernel(const void* __restrict__ ei, const float* __restrict__ ew)
{
    const int e = blockIdx.x * blockDim.x + threadIdx.x;
    if (e < EE) {
        const int row = idx_at(ei, e);
        const int col = idx_at(ei, e + EE);
        const int p = g_starts[col] + atomicAdd(&g_cur[col], 1);
        g_srcA[p] = row;
        g_wA[p] = -g_dis[row] * ew[e] * g_dis[col];
    }
}

// ---------------- sparse propagation ----------------
__global__ __launch_bounds__(64)
void prop_kernel(int xsel, const float* __restrict__ xext, int xoff, int ldx,
                 int x0sel, const float* __restrict__ x0ext, int x0off, int ldx0,
                 int osel, int mode)
{
    const float* X  = resolve_c(xsel, xext, xoff);
    const float* X0 = (mode ? resolve_c(x0sel, x0ext, x0off) : nullptr);
    float* out = resolve_w(osel, 0);
    const int n = blockIdx.x;
    const int t = threadIdx.x;
    const int s0 = g_starts[n];
    const int s1 = g_starts[n + 1];
    float4 a = make_float4(0, 0, 0, 0);
    float4 b = make_float4(0, 0, 0, 0);
    int i = s0;
    for (; i + 1 < s1; i += 2) {
        const float w0 = g_wA[i];
        const float w1 = g_wA[i + 1];
        const int r0 = g_srcA[i];
        const int r1 = g_srcA[i + 1];
        const float4 x0 = *(const float4*)(X + (size_t)r0 * ldx + (t << 2));
        const float4 x1 = *(const float4*)(X + (size_t)r1 * ldx + (t << 2));
        a.x += w0 * x0.x; a.y += w0 * x0.y; a.z += w0 * x0.z; a.w += w0 * x0.w;
        b.x += w1 * x1.x; b.y += w1 * x1.y; b.z += w1 * x1.z; b.w += w1 * x1.w;
    }
    if (i < s1) {
        const float w0 = g_wA[i];
        const int r0 = g_srcA[i];
        const float4 x0 = *(const float4*)(X + (size_t)r0 * ldx + (t << 2));
        a.x += w0 * x0.x; a.y += w0 * x0.y; a.z += w0 * x0.z; a.w += w0 * x0.w;
    }
    float4 r = make_float4(a.x + b.x, a.y + b.y, a.z + b.z, a.w + b.w);
    if (mode) {
        const float4 xv = *(const float4*)(X0 + (size_t)n * ldx0 + (t << 2));
        r.x = 2.f * r.x - xv.x;
        r.y = 2.f * r.y - xv.y;
        r.z = 2.f * r.z - xv.z;
        r.w = 2.f * r.w - xv.w;
    }
    *(float4*)(out + (size_t)n * 256 + (t << 2)) = r;
}

// ---------------- final tiny GEMM: logit = z @ cls_w2 + b2 ----------------
__global__ void logits_kernel(const float* __restrict__ w2, const float* __restrict__ b2,
                              float* __restrict__ out)
{
    const int n = blockIdx.x * 8 + (threadIdx.x >> 5);
    const int lane = threadIdx.x & 31;
    if (n >= NN) return;
    float a0 = 0.f, a1 = 0.f;
    const float* z = g_z + (size_t)n * 256;
    for (int i = lane; i < 256; i += 32) {
        const float zv = z[i];
        a0 += zv * w2[2 * i];
        a1 += zv * w2[2 * i + 1];
    }
#pragma unroll
    for (int off = 16; off > 0; off >>= 1) {
        a0 += __shfl_xor_sync(0xffffffffu, a0, off);
        a1 += __shfl_xor_sync(0xffffffffu, a1, off);
    }
    if (lane == 0) {
        out[2 * n] = a0 + b2[0];
        out[2 * n + 1] = a1 + b2[1];
    }
}

// ---------------- launch ----------------
extern "C" void kernel_launch(void* const* d_in, const int* in_sizes, int n_in,
                              void* d_out, int out_size)
{
    (void)in_sizes; (void)n_in; (void)out_size;
    const float* features = (const float*)d_in[0];
    const void*  ei       = d_in[1];
    const float* edgenet  = (const float*)d_in[2];
    const float* cheb     = (const float*)d_in[3];
    const float* en_w1    = (const float*)d_in[4];
    const float* en_b1    = (const float*)d_in[5];
    const float* en_g1    = (const float*)d_in[6];
    const float* en_be1   = (const float*)d_in[7];
    const float* en_w2    = (const float*)d_in[8];
    const float* en_b2    = (const float*)d_in[9];
    const float* cls_w1   = (const float*)d_in[10];
    const float* cls_b1   = (const float*)d_in[11];
    const float* cls_g    = (const float*)d_in[12];
    const float* cls_b    = (const float*)d_in[13];
    const float* cls_w2   = (const float*)d_in[14];
    const float* cls_b2   = (const float*)d_in[15];
    float* out = (float*)d_out;
    float* ew  = out + NN * 2;

    cudaFuncSetAttribute(edge_hmma_kernel,
                         cudaFuncAttributeMaxDynamicSharedMemorySize, ESMEM);
    cudaFuncSetAttribute(hmma_kernel<1>,
                         cudaFuncAttributeMaxDynamicSharedMemorySize, HSMEM);
    cudaFuncSetAttribute(hmma_kernel<2>,
                         cudaFuncAttributeMaxDynamicSharedMemorySize, HSMEM);

    detect_kernel<<<1, 32>>>(ei);
    zero_kernel<<<(NN + 255) / 256, 256>>>();
    split_weights_kernel<<<(WTOTAL + 255) / 256, 256>>>(cheb, cls_w1, en_w1, en_w2);

    edge_hmma_kernel<<<148, 256, ESMEM>>>(edgenet, en_b1, en_g1, en_be1, en_b2, ew);

    degcnt_kernel<<<(EE + 255) / 256, 256>>>(ei, ew);
    dis_kernel<<<(NN + 255) / 256, 256>>>();
    scan_kernel<<<1, 1024>>>();
    fill_kernel<<<(EE + 255) / 256, 256>>>(ei, ew);

    const int mtiles = (NN + 127) / 128;
    for (int l = 0; l < 4; l++) {
        const int xsel = (l == 0) ? SEL_EXT : SEL_JK;
        const int xoff = (l == 0) ? 0 : (l - 1) * 256;
        const int ldx  = (l == 0) ? 256 : 1024;
        prop_kernel<<<NN, 64>>>(xsel, features, xoff, ldx,
                                0, nullptr, 0, 0, SEL_T1, 0);
        prop_kernel<<<NN, 64>>>(SEL_T1, nullptr, 0, 256,
                                xsel, features, xoff, ldx, SEL_T2, 1);
        dim3 gC(mtiles, 2);
        hmma_kernel<2><<<gC, 256, HSMEM>>>(
            xsel, features, xoff, ldx,
            (l * 3) * 65536, 3, 8, 256,
            SEL_JK, l * 256, 1024, NN,
            nullptr, nullptr, nullptr);
    }

    dim3 gZ(mtiles, 2);
    hmma_kernel<1><<<gZ, 256, HSMEM>>>(
        SEL_JK, nullptr, 0, 1024,
        CLS_OFF, 1, 32, 256,
        SEL_Z, 0, 256, NN,
        cls_b1, cls_g, cls_b);
    logits_kernel<<<NN / 8, 256>>>(cls_w2, cls_b2, out);
}